// round 1
// baseline (speedup 1.0000x reference)
#include <cuda_runtime.h>
#include <cuda_bf16.h>
#include <math.h>

// Problem constants
#define B_  4
#define S_  2048
#define D_  1024
#define M_TOK (B_ * S_)            // 8192 tokens

// Scratch (device globals: allocation inside kernel_launch is forbidden)
__device__ float g_Q[M_TOK * D_];          // 32 MB
__device__ float g_K[M_TOK * D_];          // 32 MB
__device__ float g_V[M_TOK * D_];          // 32 MB
__device__ float g_H[M_TOK * D_];          // 32 MB
__device__ float g_S[B_ * S_ * S_];        // 64 MB (scores / probs)

// ---------------------------------------------------------------------------
// Tiled SGEMM, C = alpha * A * B   (NN)  or  alpha * A * B^T (NT)
// BM=BN=128, BK=8, 256 threads, 8x8 per-thread micro-tile.
// All problem dims are multiples of the tiles -> no bounds checks.
// Batched via blockIdx.z with explicit strides.
// ---------------------------------------------------------------------------
#define BM 128
#define BN 128
#define BK 8
#define TM 8
#define TN 8

__global__ __launch_bounds__(256, 2)
void gemm_nn(const float* __restrict__ A, const float* __restrict__ B,
             float* __restrict__ C, int M, int N, int K,
             long sA, long sB, long sC, float alpha)
{
    A += (long)blockIdx.z * sA;
    B += (long)blockIdx.z * sB;
    C += (long)blockIdx.z * sC;

    __shared__ float As[BK][BM];
    __shared__ float Bs[BK][BN];

    const int tid  = threadIdx.x;
    const int trow = tid >> 4;      // 0..15 (M)
    const int tcol = tid & 15;      // 0..15 (N)

    // A tile loaders: 128 rows x 8 k, float4 along K
    const int aRow  = tid >> 1;           // 0..127
    const int aCol4 = (tid & 1) * 4;      // 0 or 4
    // B tile loaders: 8 k x 128 n, float4 along N
    const int bRow  = tid >> 5;           // 0..7
    const int bCol4 = (tid & 31) * 4;     // 0..124

    const float* Ap = A + (long)(blockIdx.y * BM + aRow) * K + aCol4;
    const float* Bp = B + (long)bRow * N + blockIdx.x * BN + bCol4;

    float acc[TM][TN];
    #pragma unroll
    for (int i = 0; i < TM; i++)
        #pragma unroll
        for (int j = 0; j < TN; j++) acc[i][j] = 0.f;

    for (int k0 = 0; k0 < K; k0 += BK) {
        float4 av = *(const float4*)(Ap + k0);
        As[aCol4 + 0][aRow] = av.x;
        As[aCol4 + 1][aRow] = av.y;
        As[aCol4 + 2][aRow] = av.z;
        As[aCol4 + 3][aRow] = av.w;
        *(float4*)&Bs[bRow][bCol4] = *(const float4*)(Bp + (long)k0 * N);
        __syncthreads();

        #pragma unroll
        for (int k = 0; k < BK; k++) {
            float4 a0 = *(const float4*)&As[k][trow * TM];
            float4 a1 = *(const float4*)&As[k][trow * TM + 4];
            float4 b0 = *(const float4*)&Bs[k][tcol * TN];
            float4 b1 = *(const float4*)&Bs[k][tcol * TN + 4];
            float ar[TM] = {a0.x, a0.y, a0.z, a0.w, a1.x, a1.y, a1.z, a1.w};
            float br[TN] = {b0.x, b0.y, b0.z, b0.w, b1.x, b1.y, b1.z, b1.w};
            #pragma unroll
            for (int i = 0; i < TM; i++)
                #pragma unroll
                for (int j = 0; j < TN; j++)
                    acc[i][j] += ar[i] * br[j];
        }
        __syncthreads();
    }

    float* Cp = C + (long)(blockIdx.y * BM + trow * TM) * N
                  + blockIdx.x * BN + tcol * TN;
    #pragma unroll
    for (int i = 0; i < TM; i++) {
        float4 o0 = make_float4(acc[i][0] * alpha, acc[i][1] * alpha,
                                acc[i][2] * alpha, acc[i][3] * alpha);
        float4 o1 = make_float4(acc[i][4] * alpha, acc[i][5] * alpha,
                                acc[i][6] * alpha, acc[i][7] * alpha);
        *(float4*)(Cp + (long)i * N)     = o0;
        *(float4*)(Cp + (long)i * N + 4) = o1;
    }
}

// C[m,n] = alpha * sum_k A[m,k] * B[n,k]   (both row-major [.,K])
__global__ __launch_bounds__(256, 2)
void gemm_nt(const float* __restrict__ A, const float* __restrict__ B,
             float* __restrict__ C, int M, int N, int K,
             long sA, long sB, long sC, float alpha)
{
    A += (long)blockIdx.z * sA;
    B += (long)blockIdx.z * sB;
    C += (long)blockIdx.z * sC;

    __shared__ float As[BK][BM];
    __shared__ float Bs[BK][BN];

    const int tid  = threadIdx.x;
    const int trow = tid >> 4;
    const int tcol = tid & 15;

    const int aRow  = tid >> 1;
    const int aCol4 = (tid & 1) * 4;

    const float* Ap = A + (long)(blockIdx.y * BM + aRow) * K + aCol4;
    const float* Bp = B + (long)(blockIdx.x * BN + aRow) * K + aCol4;  // same pattern

    float acc[TM][TN];
    #pragma unroll
    for (int i = 0; i < TM; i++)
        #pragma unroll
        for (int j = 0; j < TN; j++) acc[i][j] = 0.f;

    for (int k0 = 0; k0 < K; k0 += BK) {
        float4 av = *(const float4*)(Ap + k0);
        As[aCol4 + 0][aRow] = av.x;
        As[aCol4 + 1][aRow] = av.y;
        As[aCol4 + 2][aRow] = av.z;
        As[aCol4 + 3][aRow] = av.w;
        float4 bv = *(const float4*)(Bp + k0);
        Bs[aCol4 + 0][aRow] = bv.x;
        Bs[aCol4 + 1][aRow] = bv.y;
        Bs[aCol4 + 2][aRow] = bv.z;
        Bs[aCol4 + 3][aRow] = bv.w;
        __syncthreads();

        #pragma unroll
        for (int k = 0; k < BK; k++) {
            float4 a0 = *(const float4*)&As[k][trow * TM];
            float4 a1 = *(const float4*)&As[k][trow * TM + 4];
            float4 b0 = *(const float4*)&Bs[k][tcol * TN];
            float4 b1 = *(const float4*)&Bs[k][tcol * TN + 4];
            float ar[TM] = {a0.x, a0.y, a0.z, a0.w, a1.x, a1.y, a1.z, a1.w};
            float br[TN] = {b0.x, b0.y, b0.z, b0.w, b1.x, b1.y, b1.z, b1.w};
            #pragma unroll
            for (int i = 0; i < TM; i++)
                #pragma unroll
                for (int j = 0; j < TN; j++)
                    acc[i][j] += ar[i] * br[j];
        }
        __syncthreads();
    }

    float* Cp = C + (long)(blockIdx.y * BM + trow * TM) * N
                  + blockIdx.x * BN + tcol * TN;
    #pragma unroll
    for (int i = 0; i < TM; i++) {
        float4 o0 = make_float4(acc[i][0] * alpha, acc[i][1] * alpha,
                                acc[i][2] * alpha, acc[i][3] * alpha);
        float4 o1 = make_float4(acc[i][4] * alpha, acc[i][5] * alpha,
                                acc[i][6] * alpha, acc[i][7] * alpha);
        *(float4*)(Cp + (long)i * N)     = o0;
        *(float4*)(Cp + (long)i * N + 4) = o1;
    }
}

// ---------------------------------------------------------------------------
// In-place row softmax over rows of length 2048; one block (256 thr) per row.
// ---------------------------------------------------------------------------
__global__ __launch_bounds__(256)
void softmax_rows(float* __restrict__ S)
{
    float* row = S + (long)blockIdx.x * S_;
    const int tid  = threadIdx.x;
    const int lane = tid & 31;
    const int warp = tid >> 5;
    __shared__ float red[8];

    float v[8];
    float m = -INFINITY;
    #pragma unroll
    for (int i = 0; i < 8; i++) {
        v[i] = row[tid + i * 256];
        m = fmaxf(m, v[i]);
    }
    #pragma unroll
    for (int o = 16; o > 0; o >>= 1) m = fmaxf(m, __shfl_xor_sync(0xffffffffu, m, o));
    if (lane == 0) red[warp] = m;
    __syncthreads();
    m = red[lane & 7];
    #pragma unroll
    for (int o = 4; o > 0; o >>= 1) m = fmaxf(m, __shfl_xor_sync(0xffffffffu, m, o));
    m = __shfl_sync(0xffffffffu, m, 0);

    float s = 0.f;
    #pragma unroll
    for (int i = 0; i < 8; i++) {
        v[i] = __expf(v[i] - m);
        s += v[i];
    }
    #pragma unroll
    for (int o = 16; o > 0; o >>= 1) s += __shfl_xor_sync(0xffffffffu, s, o);
    __syncthreads();
    if (lane == 0) red[warp] = s;
    __syncthreads();
    s = red[lane & 7];
    #pragma unroll
    for (int o = 4; o > 0; o >>= 1) s += __shfl_xor_sync(0xffffffffu, s, o);
    s = __shfl_sync(0xffffffffu, s, 0);

    const float inv = 1.f / s;
    #pragma unroll
    for (int i = 0; i < 8; i++) row[tid + i * 256] = v[i] * inv;
}

// ---------------------------------------------------------------------------
extern "C" void kernel_launch(void* const* d_in, const int* in_sizes, int n_in,
                              void* d_out, int out_size)
{
    const float* X  = (const float*)d_in[0];
    const float* WQ = (const float*)d_in[1];
    const float* WK = (const float*)d_in[2];
    const float* WV = (const float*)d_in[3];
    const float* WO = (const float*)d_in[4];
    float* Y = (float*)d_out;

    float *Q, *K, *V, *H, *Ssc;
    cudaGetSymbolAddress((void**)&Q,   g_Q);
    cudaGetSymbolAddress((void**)&K,   g_K);
    cudaGetSymbolAddress((void**)&V,   g_V);
    cudaGetSymbolAddress((void**)&H,   g_H);
    cudaGetSymbolAddress((void**)&Ssc, g_S);

    dim3 thr(256);

    // Projections: [8192,1024] = X[8192,1024] x W[1024,1024]
    dim3 gProj(D_ / BN, M_TOK / BM, 1);
    gemm_nn<<<gProj, thr>>>(X, WQ, Q, M_TOK, D_, D_, 0, 0, 0, 1.0f);
    gemm_nn<<<gProj, thr>>>(X, WK, K, M_TOK, D_, D_, 0, 0, 0, 1.0f);
    gemm_nn<<<gProj, thr>>>(X, WV, V, M_TOK, D_, D_, 0, 0, 0, 1.0f);

    // Scores: per batch S[2048,2048] = Q[2048,1024] x K^T, scaled by 1/sqrt(Dk)
    dim3 gScore(S_ / BN, S_ / BM, B_);
    gemm_nt<<<gScore, thr>>>(Q, K, Ssc, S_, S_, D_,
                             (long)S_ * D_, (long)S_ * D_, (long)S_ * S_,
                             1.0f / 32.0f);

    // Softmax over all 8192 rows of length 2048
    softmax_rows<<<B_ * S_, thr>>>(Ssc);

    // H: per batch [2048,1024] = A[2048,2048] x V[2048,1024]
    dim3 gAV(D_ / BN, S_ / BM, B_);
    gemm_nn<<<gAV, thr>>>(Ssc, V, H, S_, D_, S_,
                          (long)S_ * S_, (long)S_ * D_, (long)S_ * D_, 1.0f);

    // Output: [8192,1024] = H x W_O
    gemm_nn<<<gProj, thr>>>(H, WO, Y, M_TOK, D_, D_, 0, 0, 0, 1.0f);
}

// round 3
// speedup vs baseline: 2.1167x; 2.1167x over previous
#include <cuda_runtime.h>
#include <cuda_bf16.h>
#include <math.h>
#include <stdint.h>

// ---------------------------------------------------------------------------
// Problem constants
// ---------------------------------------------------------------------------
#define B_  4
#define S_  2048
#define D_  1024
#define M_TOK (B_ * S_)            // 8192

// ---------------------------------------------------------------------------
// Scratch (device globals; allocation in kernel_launch is forbidden)
// ---------------------------------------------------------------------------
__device__ __nv_bfloat16 g_Xhi[M_TOK * D_];
__device__ __nv_bfloat16 g_Xlo[M_TOK * D_];
__device__ __nv_bfloat16 g_WQthi[D_ * D_], g_WQtlo[D_ * D_];
__device__ __nv_bfloat16 g_WKthi[D_ * D_], g_WKtlo[D_ * D_];
__device__ __nv_bfloat16 g_WVthi[D_ * D_], g_WVtlo[D_ * D_];
__device__ __nv_bfloat16 g_WOthi[D_ * D_], g_WOtlo[D_ * D_];
__device__ __nv_bfloat16 g_Qhi[M_TOK * D_], g_Qlo[M_TOK * D_];
__device__ __nv_bfloat16 g_Khi[M_TOK * D_], g_Klo[M_TOK * D_];
__device__ float         g_Vf [M_TOK * D_];
__device__ __nv_bfloat16 g_Vthi[M_TOK * D_], g_Vtlo[M_TOK * D_];
__device__ float         g_Sc [B_ * S_ * S_];
__device__ __nv_bfloat16 g_Phi[(long)B_ * S_ * S_], g_Plo[(long)B_ * S_ * S_];
__device__ __nv_bfloat16 g_Hhi[M_TOK * D_], g_Hlo[M_TOK * D_];

// ---------------------------------------------------------------------------
// Helpers
// ---------------------------------------------------------------------------
__device__ __forceinline__ uint32_t smem_u32(const void* p) {
    uint32_t a;
    asm("{ .reg .u64 t; cvta.to.shared.u64 t, %1; cvt.u32.u64 %0, t; }"
        : "=r"(a) : "l"(p));
    return a;
}

#define CP16(dst, src) \
    asm volatile("cp.async.cg.shared.global [%0], [%1], 16;" \
                 :: "r"((uint32_t)(dst)), "l"(src))

#define LDMX4(r, addr) \
    asm volatile("ldmatrix.sync.aligned.m8n8.x4.shared.b16 {%0,%1,%2,%3}, [%4];" \
                 : "=r"((r)[0]), "=r"((r)[1]), "=r"((r)[2]), "=r"((r)[3]) \
                 : "r"(addr))

// Not volatile: let ptxas schedule/interleave independent MMA chains.
#define MMA_BF16(d, a, b0, b1) \
    asm("mma.sync.aligned.m16n8k16.row.col.f32.bf16.bf16.f32 " \
        "{%0,%1,%2,%3}, {%4,%5,%6,%7}, {%8,%9}, {%0,%1,%2,%3};" \
        : "+f"((d)[0]), "+f"((d)[1]), "+f"((d)[2]), "+f"((d)[3]) \
        : "r"((a)[0]), "r"((a)[1]), "r"((a)[2]), "r"((a)[3]), \
          "r"(b0), "r"(b1))

// ---------------------------------------------------------------------------
// Split-precision bf16 mma.sync GEMM:
//   C[M,N] = alpha * (Ahi+Alo)[M,K] · (Bhi+Blo)[N,K]^T
// (3 terms: hi*hi + hi*lo + lo*hi, fp32 accumulate)
// A row-major [M,K], B row-major [N,K], bf16. mode 0: fp32 C. mode 1: bf16
// hi/lo C. Batched via blockIdx.z (element strides sA/sB/sC).
// CTA tile 128x128, BK=32, 256 threads (8 warps, warp tile 32x64),
// cp.async double-buffered SMEM, 80B row pitch (conflict-free ldmatrix).
// ---------------------------------------------------------------------------
#define ROWB 80
#define TILE_B (128 * ROWB)          // 10240
#define OFF_ALO TILE_B
#define OFF_BHI (2 * TILE_B)
#define OFF_BLO (3 * TILE_B)
#define STAGE_B (4 * TILE_B)         // 40960
#define GEMM_SMEM_BYTES (2 * STAGE_B)  // 81920

__global__ __launch_bounds__(256)
void gemm3(const __nv_bfloat16* __restrict__ Ahi, const __nv_bfloat16* __restrict__ Alo,
           const __nv_bfloat16* __restrict__ Bhi, const __nv_bfloat16* __restrict__ Blo,
           float* __restrict__ Cf,
           __nv_bfloat16* __restrict__ Chi, __nv_bfloat16* __restrict__ Clo,
           int K, int N, long sA, long sB, long sC, float alpha, int mode)
{
    extern __shared__ char smem[];
    const uint32_t sb = smem_u32(smem);
    const int tid  = threadIdx.x;
    const int wid  = tid >> 5;
    const int lane = tid & 31;
    const long z   = blockIdx.z;

    // ---- global->smem load geometry: thread handles one 32B half-row/tile
    const int glr = tid >> 1;                 // tile row 0..127
    const int glc = (tid & 1) * 32;           // byte col 0 or 32
    const long rowA = (long)blockIdx.y * 128;
    const long rowB = (long)blockIdx.x * 128;
    const char* pAhi = (const char*)(Ahi + z * sA + (rowA + glr) * (long)K) + glc;
    const char* pAlo = (const char*)(Alo + z * sA + (rowA + glr) * (long)K) + glc;
    const char* pBhi = (const char*)(Bhi + z * sB + (rowB + glr) * (long)K) + glc;
    const char* pBlo = (const char*)(Blo + z * sB + (rowB + glr) * (long)K) + glc;
    const uint32_t sdst = sb + (uint32_t)(glr * ROWB + glc);

    // ---- ldmatrix geometry
    const int warp_m = wid & 3;               // 4 m-slices of 32
    const int warp_n = wid >> 2;              // 2 n-slices of 64
    const int quad = lane >> 3;
    const int lr8  = lane & 7;
    // lanes 0-7: rows+0 (k-lo), 8-15: rows+8 (k-lo), 16-23: rows+0 (k-hi), 24-31: rows+8 (k-hi)
    const uint32_t aBase = sb + (uint32_t)((warp_m * 32 + lr8 + (quad & 1) * 8) * ROWB
                                           + (quad >> 1) * 16);
    const uint32_t bBase = sb + OFF_BHI + (uint32_t)((warp_n * 64 + lr8 + (quad & 1) * 8) * ROWB
                                                     + (quad >> 1) * 16);

    float acc[2][8][4];
    #pragma unroll
    for (int mt = 0; mt < 2; mt++)
        #pragma unroll
        for (int nf = 0; nf < 8; nf++)
            #pragma unroll
            for (int q = 0; q < 4; q++) acc[mt][nf][q] = 0.f;

    const int nc = K >> 5;                    // K / 32

    // prologue: stage 0
    {
        uint32_t d = sdst;
        CP16(d,            pAhi);      CP16(d + 16,            pAhi + 16);
        CP16(d + OFF_ALO,  pAlo);      CP16(d + OFF_ALO + 16,  pAlo + 16);
        CP16(d + OFF_BHI,  pBhi);      CP16(d + OFF_BHI + 16,  pBhi + 16);
        CP16(d + OFF_BLO,  pBlo);      CP16(d + OFF_BLO + 16,  pBlo + 16);
        asm volatile("cp.async.commit_group;" ::: "memory");
    }

    for (int i = 0; i < nc; i++) {
        if (i + 1 < nc) {
            const long ko = (long)(i + 1) * 64;   // 32 bf16 = 64B per step
            uint32_t d = sdst + ((i + 1) & 1) * STAGE_B;
            CP16(d,            pAhi + ko);  CP16(d + 16,            pAhi + ko + 16);
            CP16(d + OFF_ALO,  pAlo + ko);  CP16(d + OFF_ALO + 16,  pAlo + ko + 16);
            CP16(d + OFF_BHI,  pBhi + ko);  CP16(d + OFF_BHI + 16,  pBhi + ko + 16);
            CP16(d + OFF_BLO,  pBlo + ko);  CP16(d + OFF_BLO + 16,  pBlo + ko + 16);
            asm volatile("cp.async.commit_group;" ::: "memory");
            asm volatile("cp.async.wait_group 1;" ::: "memory");
        } else {
            asm volatile("cp.async.wait_group 0;" ::: "memory");
        }
        __syncthreads();

        const uint32_t stA = aBase + (i & 1) * STAGE_B;
        const uint32_t stB = bBase + (i & 1) * STAGE_B;

        #pragma unroll
        for (int ks = 0; ks < 2; ks++) {
            uint32_t ah[2][4], al[2][4];
            #pragma unroll
            for (int mt = 0; mt < 2; mt++) {
                uint32_t ad = stA + mt * (16 * ROWB) + ks * 32;
                LDMX4(ah[mt], ad);
                LDMX4(al[mt], ad + TILE_B);
            }
            #pragma unroll
            for (int ng = 0; ng < 4; ng++) {
                uint32_t bh[4], bl[4];
                uint32_t bd = stB + ng * (16 * ROWB) + ks * 32;
                LDMX4(bh, bd);
                LDMX4(bl, bd + TILE_B);
                // x4 gives frags: n-lo = {r0,r2}, n-hi = {r1,r3}
                #pragma unroll
                for (int mt = 0; mt < 2; mt++) {
                    MMA_BF16(acc[mt][ng * 2 + 0], ah[mt], bh[0], bh[2]);
                    MMA_BF16(acc[mt][ng * 2 + 1], ah[mt], bh[1], bh[3]);
                }
                #pragma unroll
                for (int mt = 0; mt < 2; mt++) {
                    MMA_BF16(acc[mt][ng * 2 + 0], ah[mt], bl[0], bl[2]);
                    MMA_BF16(acc[mt][ng * 2 + 1], ah[mt], bl[1], bl[3]);
                }
                #pragma unroll
                for (int mt = 0; mt < 2; mt++) {
                    MMA_BF16(acc[mt][ng * 2 + 0], al[mt], bh[0], bh[2]);
                    MMA_BF16(acc[mt][ng * 2 + 1], al[mt], bh[1], bh[3]);
                }
            }
        }
        __syncthreads();
    }

    // ---- epilogue
    const long baseM = (long)blockIdx.y * 128 + warp_m * 32;
    const long baseN = (long)blockIdx.x * 128 + warp_n * 64;
    const int rq = lane >> 2;                 // row within 8
    const int cq = (lane & 3) * 2;            // col pair
    #pragma unroll
    for (int mt = 0; mt < 2; mt++) {
        #pragma unroll
        for (int nf = 0; nf < 8; nf++) {
            const long r0 = baseM + mt * 16 + rq;
            const long c0 = baseN + nf * 8 + cq;
            float v0 = acc[mt][nf][0] * alpha;
            float v1 = acc[mt][nf][1] * alpha;
            float v2 = acc[mt][nf][2] * alpha;
            float v3 = acc[mt][nf][3] * alpha;
            if (mode == 0) {
                float* o0 = Cf + z * sC + r0 * (long)N + c0;
                float* o1 = o0 + 8 * (long)N;
                *(float2*)o0 = make_float2(v0, v1);
                *(float2*)o1 = make_float2(v2, v3);
            } else {
                __nv_bfloat16 h0 = __float2bfloat16(v0);
                __nv_bfloat16 h1 = __float2bfloat16(v1);
                __nv_bfloat16 h2 = __float2bfloat16(v2);
                __nv_bfloat16 h3 = __float2bfloat16(v3);
                __nv_bfloat16 l0 = __float2bfloat16(v0 - __bfloat162float(h0));
                __nv_bfloat16 l1 = __float2bfloat16(v1 - __bfloat162float(h1));
                __nv_bfloat16 l2 = __float2bfloat16(v2 - __bfloat162float(h2));
                __nv_bfloat16 l3 = __float2bfloat16(v3 - __bfloat162float(h3));
                __nv_bfloat16* oh0 = Chi + z * sC + r0 * (long)N + c0;
                __nv_bfloat16* ol0 = Clo + z * sC + r0 * (long)N + c0;
                *(__nv_bfloat162*)oh0 = __nv_bfloat162(h0, h1);
                *(__nv_bfloat162*)(oh0 + 8 * (long)N) = __nv_bfloat162(h2, h3);
                *(__nv_bfloat162*)ol0 = __nv_bfloat162(l0, l1);
                *(__nv_bfloat162*)(ol0 + 8 * (long)N) = __nv_bfloat162(l2, l3);
            }
        }
    }
}

// ---------------------------------------------------------------------------
// fp32 -> bf16 hi/lo elementwise split
// ---------------------------------------------------------------------------
__global__ void cvt_split(const float* __restrict__ in,
                          __nv_bfloat16* __restrict__ hi,
                          __nv_bfloat16* __restrict__ lo, int n)
{
    int i = blockIdx.x * blockDim.x + threadIdx.x;
    if (i >= n) return;
    float v = in[i];
    __nv_bfloat16 h = __float2bfloat16(v);
    hi[i] = h;
    lo[i] = __float2bfloat16(v - __bfloat162float(h));
}

// ---------------------------------------------------------------------------
// fp32 [R,C] -> transposed bf16 hi/lo [C,R] (batched)
// ---------------------------------------------------------------------------
__global__ void tconv(const float* __restrict__ in,
                      __nv_bfloat16* __restrict__ hi,
                      __nv_bfloat16* __restrict__ lo,
                      int R, int C, long sIn, long sOut)
{
    __shared__ float t[32][33];
    const float* ip = in + (long)blockIdx.z * sIn;
    const int c0 = blockIdx.x * 32, r0 = blockIdx.y * 32;
    const int tx = threadIdx.x, ty = threadIdx.y;
    #pragma unroll
    for (int j = 0; j < 4; j++)
        t[ty + 8 * j][tx] = ip[(long)(r0 + ty + 8 * j) * C + c0 + tx];
    __syncthreads();
    const long ob = (long)blockIdx.z * sOut;
    #pragma unroll
    for (int j = 0; j < 4; j++) {
        float v = t[tx][ty + 8 * j];
        long o = ob + (long)(c0 + ty + 8 * j) * R + r0 + tx;
        __nv_bfloat16 h = __float2bfloat16(v);
        hi[o] = h;
        lo[o] = __float2bfloat16(v - __bfloat162float(h));
    }
}

// ---------------------------------------------------------------------------
// Row softmax over length-2048 rows; fp32 in, bf16 hi/lo out.
// ---------------------------------------------------------------------------
__global__ __launch_bounds__(256)
void softmax_rows(const float* __restrict__ S,
                  __nv_bfloat16* __restrict__ Phi,
                  __nv_bfloat16* __restrict__ Plo)
{
    const long base = (long)blockIdx.x * S_;
    const float* row = S + base;
    const int tid  = threadIdx.x;
    const int lane = tid & 31;
    const int warp = tid >> 5;
    __shared__ float red[8];

    float v[8];
    float m = -INFINITY;
    #pragma unroll
    for (int i = 0; i < 8; i++) {
        v[i] = row[tid + i * 256];
        m = fmaxf(m, v[i]);
    }
    #pragma unroll
    for (int o = 16; o > 0; o >>= 1) m = fmaxf(m, __shfl_xor_sync(0xffffffffu, m, o));
    if (lane == 0) red[warp] = m;
    __syncthreads();
    m = red[lane & 7];
    #pragma unroll
    for (int o = 4; o > 0; o >>= 1) m = fmaxf(m, __shfl_xor_sync(0xffffffffu, m, o));
    m = __shfl_sync(0xffffffffu, m, 0);

    float s = 0.f;
    #pragma unroll
    for (int i = 0; i < 8; i++) {
        v[i] = __expf(v[i] - m);
        s += v[i];
    }
    #pragma unroll
    for (int o = 16; o > 0; o >>= 1) s += __shfl_xor_sync(0xffffffffu, s, o);
    __syncthreads();
    if (lane == 0) red[warp] = s;
    __syncthreads();
    s = red[lane & 7];
    #pragma unroll
    for (int o = 4; o > 0; o >>= 1) s += __shfl_xor_sync(0xffffffffu, s, o);
    s = __shfl_sync(0xffffffffu, s, 0);

    const float inv = 1.f / s;
    #pragma unroll
    for (int i = 0; i < 8; i++) {
        float p = v[i] * inv;
        __nv_bfloat16 h = __float2bfloat16(p);
        Phi[base + tid + i * 256] = h;
        Plo[base + tid + i * 256] = __float2bfloat16(p - __bfloat162float(h));
    }
}

// ---------------------------------------------------------------------------
extern "C" void kernel_launch(void* const* d_in, const int* in_sizes, int n_in,
                              void* d_out, int out_size)
{
    const float* X  = (const float*)d_in[0];
    const float* WQ = (const float*)d_in[1];
    const float* WK = (const float*)d_in[2];
    const float* WV = (const float*)d_in[3];
    const float* WO = (const float*)d_in[4];
    float* Y = (float*)d_out;

    __nv_bfloat16 *Xhi, *Xlo, *WQthi, *WQtlo, *WKthi, *WKtlo, *WVthi, *WVtlo,
                  *WOthi, *WOtlo, *Qhi, *Qlo, *Khi, *Klo, *Vthi, *Vtlo,
                  *Phi, *Plo, *Hhi, *Hlo;
    float *Vf, *Sc;
    cudaGetSymbolAddress((void**)&Xhi,   g_Xhi);
    cudaGetSymbolAddress((void**)&Xlo,   g_Xlo);
    cudaGetSymbolAddress((void**)&WQthi, g_WQthi);
    cudaGetSymbolAddress((void**)&WQtlo, g_WQtlo);
    cudaGetSymbolAddress((void**)&WKthi, g_WKthi);
    cudaGetSymbolAddress((void**)&WKtlo, g_WKtlo);
    cudaGetSymbolAddress((void**)&WVthi, g_WVthi);
    cudaGetSymbolAddress((void**)&WVtlo, g_WVtlo);
    cudaGetSymbolAddress((void**)&WOthi, g_WOthi);
    cudaGetSymbolAddress((void**)&WOtlo, g_WOtlo);
    cudaGetSymbolAddress((void**)&Qhi,   g_Qhi);
    cudaGetSymbolAddress((void**)&Qlo,   g_Qlo);
    cudaGetSymbolAddress((void**)&Khi,   g_Khi);
    cudaGetSymbolAddress((void**)&Klo,   g_Klo);
    cudaGetSymbolAddress((void**)&Vf,    g_Vf);
    cudaGetSymbolAddress((void**)&Vthi,  g_Vthi);
    cudaGetSymbolAddress((void**)&Vtlo,  g_Vtlo);
    cudaGetSymbolAddress((void**)&Sc,    g_Sc);
    cudaGetSymbolAddress((void**)&Phi,   g_Phi);
    cudaGetSymbolAddress((void**)&Plo,   g_Plo);
    cudaGetSymbolAddress((void**)&Hhi,   g_Hhi);
    cudaGetSymbolAddress((void**)&Hlo,   g_Hlo);

    cudaFuncSetAttribute(gemm3, cudaFuncAttributeMaxDynamicSharedMemorySize,
                         GEMM_SMEM_BYTES);

    dim3 thr(256);
    const size_t smb = GEMM_SMEM_BYTES;

    // Input conversions
    cvt_split<<<(M_TOK * D_) / 256, thr>>>(X, Xhi, Xlo, M_TOK * D_);
    dim3 tW(32, 8);
    tconv<<<dim3(32, 32, 1), tW>>>(WQ, WQthi, WQtlo, D_, D_, 0, 0);
    tconv<<<dim3(32, 32, 1), tW>>>(WK, WKthi, WKtlo, D_, D_, 0, 0);
    tconv<<<dim3(32, 32, 1), tW>>>(WV, WVthi, WVtlo, D_, D_, 0, 0);
    tconv<<<dim3(32, 32, 1), tW>>>(WO, WOthi, WOtlo, D_, D_, 0, 0);

    // Q, K projections: [8192,1024] = X · Wt^T   -> bf16 hi/lo out
    gemm3<<<dim3(8, 64, 1), thr, smb>>>(Xhi, Xlo, WQthi, WQtlo,
                                        nullptr, Qhi, Qlo,
                                        D_, D_, 0, 0, 0, 1.f, 1);
    gemm3<<<dim3(8, 64, 1), thr, smb>>>(Xhi, Xlo, WKthi, WKtlo,
                                        nullptr, Khi, Klo,
                                        D_, D_, 0, 0, 0, 1.f, 1);
    // V projection -> fp32, then transpose to [1024,2048] hi/lo per batch
    gemm3<<<dim3(8, 64, 1), thr, smb>>>(Xhi, Xlo, WVthi, WVtlo,
                                        Vf, nullptr, nullptr,
                                        D_, D_, 0, 0, 0, 1.f, 0);
    tconv<<<dim3(D_ / 32, S_ / 32, B_), tW>>>(Vf, Vthi, Vtlo, S_, D_,
                                              (long)S_ * D_, (long)S_ * D_);

    // Scores: per-batch [2048,2048] = Q · K^T / 32  -> fp32
    gemm3<<<dim3(16, 16, 4), thr, smb>>>(Qhi, Qlo, Khi, Klo,
                                         Sc, nullptr, nullptr,
                                         D_, S_,
                                         (long)S_ * D_, (long)S_ * D_,
                                         (long)S_ * S_, 1.f / 32.f, 0);

    // Softmax -> probs bf16 hi/lo
    softmax_rows<<<B_ * S_, thr>>>(Sc, Phi, Plo);

    // H = A · V : per-batch [2048,1024], B operand = V^T [1024,2048] -> hi/lo
    gemm3<<<dim3(8, 16, 4), thr, smb>>>(Phi, Plo, Vthi, Vtlo,
                                        nullptr, Hhi, Hlo,
                                        S_, D_,
                                        (long)S_ * S_, (long)S_ * D_,
                                        (long)S_ * D_, 1.f, 1);

    // Output: [8192,1024] = H · WOt^T -> fp32 to d_out
    gemm3<<<dim3(8, 64, 1), thr, smb>>>(Hhi, Hlo, WOthi, WOtlo,
                                        Y, nullptr, nullptr,
                                        D_, D_, 0, 0, 0, 1.f, 0);
}

// round 5
// speedup vs baseline: 2.8631x; 1.3526x over previous
#include <cuda_runtime.h>
#include <cuda_fp16.h>
#include <math.h>
#include <stdint.h>

// ---------------------------------------------------------------------------
// Problem constants
// ---------------------------------------------------------------------------
#define B_  4
#define S_  2048
#define D_  1024
#define M_TOK (B_ * S_)            // 8192

// ---------------------------------------------------------------------------
// Scratch (device globals; allocation in kernel_launch is forbidden)
// ---------------------------------------------------------------------------
__device__ __half g_Xhi[M_TOK * D_], g_Xlo[M_TOK * D_];
__device__ __half g_WQt[D_ * D_], g_WKt[D_ * D_], g_WVt[D_ * D_], g_WOt[D_ * D_];
__device__ __half g_Qhi[M_TOK * D_], g_Qlo[M_TOK * D_];
__device__ __half g_Kh [M_TOK * D_];
__device__ float  g_Vf [M_TOK * D_];
__device__ __half g_Vth[M_TOK * D_];
__device__ float  g_Sc [B_ * S_ * S_];
__device__ __half g_Phi[(long)B_ * S_ * S_], g_Plo[(long)B_ * S_ * S_];
__device__ __half g_Hhi[M_TOK * D_], g_Hlo[M_TOK * D_];

// ---------------------------------------------------------------------------
// Helpers
// ---------------------------------------------------------------------------
__device__ __forceinline__ uint32_t smem_u32(const void* p) {
    uint32_t a;
    asm("{ .reg .u64 t; cvta.to.shared.u64 t, %1; cvt.u32.u64 %0, t; }"
        : "=r"(a) : "l"(p));
    return a;
}

#define CP16(dst, src) \
    asm volatile("cp.async.cg.shared.global [%0], [%1], 16;" \
                 :: "r"((uint32_t)(dst)), "l"(src))

#define LDMX4(r, addr) \
    asm volatile("ldmatrix.sync.aligned.m8n8.x4.shared.b16 {%0,%1,%2,%3}, [%4];" \
                 : "=r"((r)[0]), "=r"((r)[1]), "=r"((r)[2]), "=r"((r)[3]) \
                 : "r"(addr))

// fp16 in, fp32 accumulate
#define MMA_F16(d, a, b0, b1) \
    asm("mma.sync.aligned.m16n8k16.row.col.f32.f16.f16.f32 " \
        "{%0,%1,%2,%3}, {%4,%5,%6,%7}, {%8,%9}, {%0,%1,%2,%3};" \
        : "+f"((d)[0]), "+f"((d)[1]), "+f"((d)[2]), "+f"((d)[3]) \
        : "r"((a)[0]), "r"((a)[1]), "r"((a)[2]), "r"((a)[3]), \
          "r"(b0), "r"(b1))

// ---------------------------------------------------------------------------
// Split-precision fp16 mma.sync GEMM:
//   C[M,N] = alpha * (Ahi+Alo)[M,K] · Bhi[N,K]^T   (= alpha * A · fp16(B)^T)
// A row-major [M,K] hi/lo fp16, B row-major [N,K] fp16. Output modes:
//   0: fp32 C     1: fp16 hi/lo C     2: fp16 hi-only C
// Batched via blockIdx.z (element strides sA/sB/sC).
// CTA 128x128, BK=32, 256 thr (8 warps, warp tile 32x64), cp.async
// 3-stage pipeline, 80B row pitch, 2 CTAs/SM.
// ---------------------------------------------------------------------------
#define ROWB 80
#define TILE_B (128 * ROWB)          // 10240
#define OFF_ALO TILE_B
#define OFF_BHI (2 * TILE_B)
#define STAGE_B (3 * TILE_B)         // 30720
#define GEMM_SMEM_BYTES (3 * STAGE_B)  // 92160

#define LOADSTAGE(d, ko) do { \
    CP16((d),                 pAhi + (ko)); CP16((d) + 16,                pAhi + (ko) + 16); \
    CP16((d) + OFF_ALO,       pAlo + (ko)); CP16((d) + OFF_ALO + 16,      pAlo + (ko) + 16); \
    CP16((d) + OFF_BHI,       pBhi + (ko)); CP16((d) + OFF_BHI + 16,      pBhi + (ko) + 16); \
    asm volatile("cp.async.commit_group;" ::: "memory"); \
} while (0)

__global__ __launch_bounds__(256, 2)
void gemm3(const __half* __restrict__ Ahi, const __half* __restrict__ Alo,
           const __half* __restrict__ Bhi,
           float* __restrict__ Cf,
           __half* __restrict__ Chi, __half* __restrict__ Clo,
           int K, int N, long sA, long sB, long sC, float alpha, int mode)
{
    extern __shared__ char smem[];
    const uint32_t sb = smem_u32(smem);
    const int tid  = threadIdx.x;
    const int wid  = tid >> 5;
    const int lane = tid & 31;
    const long z   = blockIdx.z;

    // ---- global->smem load geometry: thread handles one 32B half-row/tile
    const int glr = tid >> 1;                 // tile row 0..127
    const int glc = (tid & 1) * 32;           // byte col 0 or 32
    const long rowA = (long)blockIdx.y * 128;
    const long rowB = (long)blockIdx.x * 128;
    const char* pAhi = (const char*)(Ahi + z * sA + (rowA + glr) * (long)K) + glc;
    const char* pAlo = (const char*)(Alo + z * sA + (rowA + glr) * (long)K) + glc;
    const char* pBhi = (const char*)(Bhi + z * sB + (rowB + glr) * (long)K) + glc;
    const uint32_t sdst = sb + (uint32_t)(glr * ROWB + glc);

    // ---- ldmatrix geometry
    const int warp_m = wid & 3;               // 4 m-slices of 32
    const int warp_n = wid >> 2;              // 2 n-slices of 64
    const int quad = lane >> 3;
    const int lr8  = lane & 7;
    const uint32_t aBase = sb + (uint32_t)((warp_m * 32 + lr8 + (quad & 1) * 8) * ROWB
                                           + (quad >> 1) * 16);
    const uint32_t bBase = sb + OFF_BHI + (uint32_t)((warp_n * 64 + lr8 + (quad & 1) * 8) * ROWB
                                                     + (quad >> 1) * 16);

    float acc[2][8][4];
    #pragma unroll
    for (int mt = 0; mt < 2; mt++)
        #pragma unroll
        for (int nf = 0; nf < 8; nf++)
            #pragma unroll
            for (int q = 0; q < 4; q++) acc[mt][nf][q] = 0.f;

    const int nc = K >> 5;                    // K / 32  (>= 32 for all calls)

    // prologue: stages 0 and 1
    LOADSTAGE(sdst, 0);
    LOADSTAGE(sdst + STAGE_B, 64);

    int s_load = 2;                           // stage written at iter i: (i+2)%3
    int s_cmp  = 0;                           // stage read at iter i: i%3

    for (int i = 0; i < nc; i++) {
        if (i + 2 < nc) {
            LOADSTAGE(sdst + s_load * STAGE_B, (long)(i + 2) * 64);
            asm volatile("cp.async.wait_group 2;" ::: "memory");
        } else if (i + 1 < nc) {
            asm volatile("cp.async.wait_group 1;" ::: "memory");
        } else {
            asm volatile("cp.async.wait_group 0;" ::: "memory");
        }
        __syncthreads();

        const uint32_t stA = aBase + s_cmp * STAGE_B;
        const uint32_t stB = bBase + s_cmp * STAGE_B;

        #pragma unroll
        for (int ks = 0; ks < 2; ks++) {
            uint32_t ah[2][4], al[2][4];
            #pragma unroll
            for (int mt = 0; mt < 2; mt++) {
                uint32_t ad = stA + mt * (16 * ROWB) + ks * 32;
                LDMX4(ah[mt], ad);
                LDMX4(al[mt], ad + TILE_B);
            }
            #pragma unroll
            for (int ng = 0; ng < 4; ng++) {
                uint32_t bh[4];
                LDMX4(bh, stB + ng * (16 * ROWB) + ks * 32);
                #pragma unroll
                for (int mt = 0; mt < 2; mt++) {
                    MMA_F16(acc[mt][ng * 2 + 0], ah[mt], bh[0], bh[2]);
                    MMA_F16(acc[mt][ng * 2 + 1], ah[mt], bh[1], bh[3]);
                }
                #pragma unroll
                for (int mt = 0; mt < 2; mt++) {
                    MMA_F16(acc[mt][ng * 2 + 0], al[mt], bh[0], bh[2]);
                    MMA_F16(acc[mt][ng * 2 + 1], al[mt], bh[1], bh[3]);
                }
            }
        }
        __syncthreads();

        s_load = (s_load == 2) ? 0 : s_load + 1;
        s_cmp  = (s_cmp  == 2) ? 0 : s_cmp  + 1;
    }

    // ---- epilogue
    const long baseM = (long)blockIdx.y * 128 + warp_m * 32;
    const long baseN = (long)blockIdx.x * 128 + warp_n * 64;
    const int rq = lane >> 2;                 // row within 8
    const int cq = (lane & 3) * 2;            // col pair
    #pragma unroll
    for (int mt = 0; mt < 2; mt++) {
        #pragma unroll
        for (int nf = 0; nf < 8; nf++) {
            const long r0 = baseM + mt * 16 + rq;
            const long c0 = baseN + nf * 8 + cq;
            float v0 = acc[mt][nf][0] * alpha;
            float v1 = acc[mt][nf][1] * alpha;
            float v2 = acc[mt][nf][2] * alpha;
            float v3 = acc[mt][nf][3] * alpha;
            if (mode == 0) {
                float* o0 = Cf + z * sC + r0 * (long)N + c0;
                *(float2*)o0 = make_float2(v0, v1);
                *(float2*)(o0 + 8 * (long)N) = make_float2(v2, v3);
            } else {
                __half h0 = __float2half_rn(v0);
                __half h1 = __float2half_rn(v1);
                __half h2 = __float2half_rn(v2);
                __half h3 = __float2half_rn(v3);
                __half* oh0 = Chi + z * sC + r0 * (long)N + c0;
                *(__half2*)oh0 = __halves2half2(h0, h1);
                *(__half2*)(oh0 + 8 * (long)N) = __halves2half2(h2, h3);
                if (mode == 1) {
                    __half l0 = __float2half_rn(v0 - __half2float(h0));
                    __half l1 = __float2half_rn(v1 - __half2float(h1));
                    __half l2 = __float2half_rn(v2 - __half2float(h2));
                    __half l3 = __float2half_rn(v3 - __half2float(h3));
                    __half* ol0 = Clo + z * sC + r0 * (long)N + c0;
                    *(__half2*)ol0 = __halves2half2(l0, l1);
                    *(__half2*)(ol0 + 8 * (long)N) = __halves2half2(l2, l3);
                }
            }
        }
    }
}

// ---------------------------------------------------------------------------
// fp32 -> fp16 hi/lo elementwise split
// ---------------------------------------------------------------------------
__global__ void cvt_split(const float* __restrict__ in,
                          __half* __restrict__ hi,
                          __half* __restrict__ lo, int n)
{
    int i = blockIdx.x * blockDim.x + threadIdx.x;
    if (i >= n) return;
    float v = in[i];
    __half h = __float2half_rn(v);
    hi[i] = h;
    lo[i] = __float2half_rn(v - __half2float(h));
}

// ---------------------------------------------------------------------------
// fp32 [R,C] -> transposed fp16 [C,R] (hi only; batched)
// ---------------------------------------------------------------------------
__global__ void tconvh(const float* __restrict__ in,
                       __half* __restrict__ hi,
                       int R, int C, long sIn, long sOut)
{
    __shared__ float t[32][33];
    const float* ip = in + (long)blockIdx.z * sIn;
    const int c0 = blockIdx.x * 32, r0 = blockIdx.y * 32;
    const int tx = threadIdx.x, ty = threadIdx.y;
    #pragma unroll
    for (int j = 0; j < 4; j++)
        t[ty + 8 * j][tx] = ip[(long)(r0 + ty + 8 * j) * C + c0 + tx];
    __syncthreads();
    const long ob = (long)blockIdx.z * sOut;
    #pragma unroll
    for (int j = 0; j < 4; j++) {
        float v = t[tx][ty + 8 * j];
        hi[ob + (long)(c0 + ty + 8 * j) * R + r0 + tx] = __float2half_rn(v);
    }
}

// ---------------------------------------------------------------------------
// Row softmax over length-2048 rows; fp32 in, fp16 hi/lo out.
// ---------------------------------------------------------------------------
__global__ __launch_bounds__(256)
void softmax_rows(const float* __restrict__ S,
                  __half* __restrict__ Phi,
                  __half* __restrict__ Plo)
{
    const long base = (long)blockIdx.x * S_;
    const float* row = S + base;
    const int tid  = threadIdx.x;
    const int lane = tid & 31;
    const int warp = tid >> 5;
    __shared__ float red[8];

    float v[8];
    float m = -INFINITY;
    #pragma unroll
    for (int i = 0; i < 8; i++) {
        v[i] = row[tid + i * 256];
        m = fmaxf(m, v[i]);
    }
    #pragma unroll
    for (int o = 16; o > 0; o >>= 1) m = fmaxf(m, __shfl_xor_sync(0xffffffffu, m, o));
    if (lane == 0) red[warp] = m;
    __syncthreads();
    m = red[lane & 7];
    #pragma unroll
    for (int o = 4; o > 0; o >>= 1) m = fmaxf(m, __shfl_xor_sync(0xffffffffu, m, o));
    m = __shfl_sync(0xffffffffu, m, 0);

    float s = 0.f;
    #pragma unroll
    for (int i = 0; i < 8; i++) {
        v[i] = __expf(v[i] - m);
        s += v[i];
    }
    #pragma unroll
    for (int o = 16; o > 0; o >>= 1) s += __shfl_xor_sync(0xffffffffu, s, o);
    __syncthreads();
    if (lane == 0) red[warp] = s;
    __syncthreads();
    s = red[lane & 7];
    #pragma unroll
    for (int o = 4; o > 0; o >>= 1) s += __shfl_xor_sync(0xffffffffu, s, o);
    s = __shfl_sync(0xffffffffu, s, 0);

    const float inv = 1.f / s;
    #pragma unroll
    for (int i = 0; i < 8; i++) {
        float p = v[i] * inv;
        __half h = __float2half_rn(p);
        Phi[base + tid + i * 256] = h;
        Plo[base + tid + i * 256] = __float2half_rn(p - __half2float(h));
    }
}

// ---------------------------------------------------------------------------
extern "C" void kernel_launch(void* const* d_in, const int* in_sizes, int n_in,
                              void* d_out, int out_size)
{
    const float* X  = (const float*)d_in[0];
    const float* WQ = (const float*)d_in[1];
    const float* WK = (const float*)d_in[2];
    const float* WV = (const float*)d_in[3];
    const float* WO = (const float*)d_in[4];
    float* Y = (float*)d_out;

    __half *Xhi, *Xlo, *WQt, *WKt, *WVt, *WOt, *Qhi, *Qlo, *Kh, *Vth,
           *Phi, *Plo, *Hhi, *Hlo;
    float *Vf, *Sc;
    cudaGetSymbolAddress((void**)&Xhi, g_Xhi);
    cudaGetSymbolAddress((void**)&Xlo, g_Xlo);
    cudaGetSymbolAddress((void**)&WQt, g_WQt);
    cudaGetSymbolAddress((void**)&WKt, g_WKt);
    cudaGetSymbolAddress((void**)&WVt, g_WVt);
    cudaGetSymbolAddress((void**)&WOt, g_WOt);
    cudaGetSymbolAddress((void**)&Qhi, g_Qhi);
    cudaGetSymbolAddress((void**)&Qlo, g_Qlo);
    cudaGetSymbolAddress((void**)&Kh,  g_Kh);
    cudaGetSymbolAddress((void**)&Vf,  g_Vf);
    cudaGetSymbolAddress((void**)&Vth, g_Vth);
    cudaGetSymbolAddress((void**)&Sc,  g_Sc);
    cudaGetSymbolAddress((void**)&Phi, g_Phi);
    cudaGetSymbolAddress((void**)&Plo, g_Plo);
    cudaGetSymbolAddress((void**)&Hhi, g_Hhi);
    cudaGetSymbolAddress((void**)&Hlo, g_Hlo);

    cudaFuncSetAttribute(gemm3, cudaFuncAttributeMaxDynamicSharedMemorySize,
                         GEMM_SMEM_BYTES);

    dim3 thr(256);
    const size_t smb = GEMM_SMEM_BYTES;

    // Input conversions
    cvt_split<<<(M_TOK * D_) / 256, thr>>>(X, Xhi, Xlo, M_TOK * D_);
    dim3 tW(32, 8);
    tconvh<<<dim3(32, 32, 1), tW>>>(WQ, WQt, D_, D_, 0, 0);
    tconvh<<<dim3(32, 32, 1), tW>>>(WK, WKt, D_, D_, 0, 0);
    tconvh<<<dim3(32, 32, 1), tW>>>(WV, WVt, D_, D_, 0, 0);
    tconvh<<<dim3(32, 32, 1), tW>>>(WO, WOt, D_, D_, 0, 0);

    // Q: hi/lo out (A of scores). K: hi only (B of scores).
    gemm3<<<dim3(8, 64, 1), thr, smb>>>(Xhi, Xlo, WQt, nullptr, Qhi, Qlo,
                                        D_, D_, 0, 0, 0, 1.f, 1);
    gemm3<<<dim3(8, 64, 1), thr, smb>>>(Xhi, Xlo, WKt, nullptr, Kh, nullptr,
                                        D_, D_, 0, 0, 0, 1.f, 2);
    // V: fp32 out, then transpose to [1024,2048] fp16 per batch (B of AV)
    gemm3<<<dim3(8, 64, 1), thr, smb>>>(Xhi, Xlo, WVt, Vf, nullptr, nullptr,
                                        D_, D_, 0, 0, 0, 1.f, 0);
    tconvh<<<dim3(D_ / 32, S_ / 32, B_), tW>>>(Vf, Vth, S_, D_,
                                               (long)S_ * D_, (long)S_ * D_);

    // Scores: per-batch [2048,2048] = Q · K^T / 32 -> fp32
    gemm3<<<dim3(16, 16, 4), thr, smb>>>(Qhi, Qlo, Kh, Sc, nullptr, nullptr,
                                         D_, S_,
                                         (long)S_ * D_, (long)S_ * D_,
                                         (long)S_ * S_, 1.f / 32.f, 0);

    // Softmax -> probs fp16 hi/lo
    softmax_rows<<<B_ * S_, thr>>>(Sc, Phi, Plo);

    // H = A · V : per-batch [2048,1024], B = V^T [1024,2048] -> fp16 hi/lo
    gemm3<<<dim3(8, 16, 4), thr, smb>>>(Phi, Plo, Vth, nullptr, Hhi, Hlo,
                                        S_, D_,
                                        (long)S_ * S_, (long)S_ * D_,
                                        (long)S_ * D_, 1.f, 1);

    // Output: [8192,1024] = H · WOt^T -> fp32 to d_out
    gemm3<<<dim3(8, 64, 1), thr, smb>>>(Hhi, Hlo, WOt, Y, nullptr, nullptr,
                                        D_, D_, 0, 0, 0, 1.f, 0);
}

// round 6
// speedup vs baseline: 3.0107x; 1.0516x over previous
#include <cuda_runtime.h>
#include <cuda_fp16.h>
#include <math.h>
#include <stdint.h>

// ---------------------------------------------------------------------------
// Problem constants
// ---------------------------------------------------------------------------
#define B_  4
#define S_  2048
#define D_  1024
#define M_TOK (B_ * S_)            // 8192

// ---------------------------------------------------------------------------
// Scratch (device globals; allocation in kernel_launch is forbidden)
// ---------------------------------------------------------------------------
__device__ __half g_Xhi[M_TOK * D_], g_Xlo[M_TOK * D_];
__device__ __half g_WQt[D_ * D_], g_WKt[D_ * D_], g_WVt[D_ * D_], g_WOt[D_ * D_];
__device__ __half g_Qhi[M_TOK * D_], g_Qlo[M_TOK * D_];
__device__ __half g_Kh [M_TOK * D_];
__device__ float  g_Vf [M_TOK * D_];
__device__ __half g_Vth[M_TOK * D_];
__device__ float  g_Sc [B_ * S_ * S_];
__device__ __half g_Phi[(long)B_ * S_ * S_], g_Plo[(long)B_ * S_ * S_];
__device__ __half g_Hhi[M_TOK * D_], g_Hlo[M_TOK * D_];

// ---------------------------------------------------------------------------
// Helpers
// ---------------------------------------------------------------------------
__device__ __forceinline__ uint32_t smem_u32(const void* p) {
    uint32_t a;
    asm("{ .reg .u64 t; cvta.to.shared.u64 t, %1; cvt.u32.u64 %0, t; }"
        : "=r"(a) : "l"(p));
    return a;
}

#define CP16(dst, src) \
    asm volatile("cp.async.cg.shared.global [%0], [%1], 16;" \
                 :: "r"((uint32_t)(dst)), "l"(src))

#define LDMX4(r, addr) \
    asm volatile("ldmatrix.sync.aligned.m8n8.x4.shared.b16 {%0,%1,%2,%3}, [%4];" \
                 : "=r"((r)[0]), "=r"((r)[1]), "=r"((r)[2]), "=r"((r)[3]) \
                 : "r"(addr))

// fp16 in, fp32 accumulate
#define MMA_F16(d, a, b0, b1) \
    asm("mma.sync.aligned.m16n8k16.row.col.f32.f16.f16.f32 " \
        "{%0,%1,%2,%3}, {%4,%5,%6,%7}, {%8,%9}, {%0,%1,%2,%3};" \
        : "+f"((d)[0]), "+f"((d)[1]), "+f"((d)[2]), "+f"((d)[3]) \
        : "r"((a)[0]), "r"((a)[1]), "r"((a)[2]), "r"((a)[3]), \
          "r"(b0), "r"(b1))

// ---------------------------------------------------------------------------
// Split-precision fp16 mma.sync GEMM:
//   C[M,N] = alpha * (Ahi+Alo)[M,K] · Bhi[N,K]^T   (= alpha * A · fp16(B)^T)
// A row-major [M,K] hi/lo fp16, B row-major [N,K] fp16. Output modes:
//   0: fp32 C     1: fp16 hi/lo C     2: fp16 hi-only C
// Batched via blockIdx.z (element strides sA/sB/sC).
// CTA tile 128x256, BK=32, 256 thr (8 warps as 2m x 4n, warp tile 64x64),
// cp.async 3-stage pipeline, 80B row pitch, 1 CTA/SM.
// ---------------------------------------------------------------------------
#define ROWB 80
#define OFF_ALO (128 * ROWB)         // 10240 : A-lo rows 128..255
#define OFF_BHI (256 * ROWB)         // 20480 : B rows 256..511
#define STAGE_B (512 * ROWB)         // 40960
#define GEMM_SMEM_BYTES (3 * STAGE_B)  // 122880

__global__ __launch_bounds__(256)
void gemm3(const __half* __restrict__ Ahi, const __half* __restrict__ Alo,
           const __half* __restrict__ Bhi,
           float* __restrict__ Cf,
           __half* __restrict__ Chi, __half* __restrict__ Clo,
           int K, int N, long sA, long sB, long sC, float alpha, int mode)
{
    extern __shared__ char smem[];
    const uint32_t sb = smem_u32(smem);
    const int tid  = threadIdx.x;
    const int wid  = tid >> 5;
    const int lane = tid & 31;
    const long z   = blockIdx.z;

    // ---- global->smem load geometry: 2048 16B chunks/stage, 8 per thread.
    // chunk c: row = c>>2 (0..511), col = (c&3)*16 bytes.
    // rows 0-127 = A-hi, 128-255 = A-lo, 256-511 = B.
    const long rowA = (long)blockIdx.y * 128;
    const long rowB = (long)blockIdx.x * 256;
    const char* gp[8];
    uint32_t sw[8];
    #pragma unroll
    for (int j = 0; j < 8; j++) {
        int c = tid + 256 * j;
        int r = c >> 2;
        int col = (c & 3) * 16;
        sw[j] = (uint32_t)(r * ROWB + col);
        if (r < 128)
            gp[j] = (const char*)(Ahi + z * sA + (rowA + r) * (long)K) + col;
        else if (r < 256)
            gp[j] = (const char*)(Alo + z * sA + (rowA + r - 128) * (long)K) + col;
        else
            gp[j] = (const char*)(Bhi + z * sB + (rowB + r - 256) * (long)K) + col;
    }

    // ---- ldmatrix geometry: warp tile 64x64
    const int warp_m = wid & 1;               // 2 m-slices of 64
    const int warp_n = wid >> 1;              // 4 n-slices of 64
    const int quad = lane >> 3;
    const int lr8  = lane & 7;
    const uint32_t aBase = sb + (uint32_t)((warp_m * 64 + lr8 + (quad & 1) * 8) * ROWB
                                           + (quad >> 1) * 16);
    const uint32_t bBase = sb + OFF_BHI + (uint32_t)((warp_n * 64 + lr8 + (quad & 1) * 8) * ROWB
                                                     + (quad >> 1) * 16);

    float acc[4][8][4];
    #pragma unroll
    for (int mf = 0; mf < 4; mf++)
        #pragma unroll
        for (int nf = 0; nf < 8; nf++)
            #pragma unroll
            for (int q = 0; q < 4; q++) acc[mf][nf][q] = 0.f;

    const int nc = K >> 5;                    // K / 32

#define LOADSTAGE(base, ko) do { \
    _Pragma("unroll") \
    for (int j = 0; j < 8; j++) CP16((base) + sw[j], gp[j] + (ko)); \
    asm volatile("cp.async.commit_group;" ::: "memory"); \
} while (0)

    // prologue: stages 0 and 1
    LOADSTAGE(sb, 0);
    LOADSTAGE(sb + STAGE_B, 64);

    int s_load = 2;
    int s_cmp  = 0;

    for (int i = 0; i < nc; i++) {
        if (i + 2 < nc) {
            LOADSTAGE(sb + s_load * STAGE_B, (long)(i + 2) * 64);
            asm volatile("cp.async.wait_group 2;" ::: "memory");
        } else if (i + 1 < nc) {
            asm volatile("cp.async.wait_group 1;" ::: "memory");
        } else {
            asm volatile("cp.async.wait_group 0;" ::: "memory");
        }
        __syncthreads();

        const uint32_t stA = aBase + s_cmp * STAGE_B;
        const uint32_t stB = bBase + s_cmp * STAGE_B;

        #pragma unroll
        for (int ks = 0; ks < 2; ks++) {
            uint32_t ah[4][4], al[4][4], bh[4][4];
            #pragma unroll
            for (int mf = 0; mf < 4; mf++) {
                uint32_t ad = stA + mf * (16 * ROWB) + ks * 32;
                LDMX4(ah[mf], ad);
                LDMX4(al[mf], ad + OFF_ALO);
            }
            #pragma unroll
            for (int ng = 0; ng < 4; ng++)
                LDMX4(bh[ng], stB + ng * (16 * ROWB) + ks * 32);

            #pragma unroll
            for (int ng = 0; ng < 4; ng++) {
                #pragma unroll
                for (int mf = 0; mf < 4; mf++) {
                    MMA_F16(acc[mf][ng * 2 + 0], ah[mf], bh[ng][0], bh[ng][2]);
                    MMA_F16(acc[mf][ng * 2 + 1], ah[mf], bh[ng][1], bh[ng][3]);
                }
                #pragma unroll
                for (int mf = 0; mf < 4; mf++) {
                    MMA_F16(acc[mf][ng * 2 + 0], al[mf], bh[ng][0], bh[ng][2]);
                    MMA_F16(acc[mf][ng * 2 + 1], al[mf], bh[ng][1], bh[ng][3]);
                }
            }
        }
        __syncthreads();

        s_load = (s_load == 2) ? 0 : s_load + 1;
        s_cmp  = (s_cmp  == 2) ? 0 : s_cmp  + 1;
    }
#undef LOADSTAGE

    // ---- epilogue
    const long baseM = (long)blockIdx.y * 128 + warp_m * 64;
    const long baseN = (long)blockIdx.x * 256 + warp_n * 64;
    const int rq = lane >> 2;                 // row within 8
    const int cq = (lane & 3) * 2;            // col pair
    #pragma unroll
    for (int mf = 0; mf < 4; mf++) {
        #pragma unroll
        for (int nf = 0; nf < 8; nf++) {
            const long r0 = baseM + mf * 16 + rq;
            const long c0 = baseN + nf * 8 + cq;
            float v0 = acc[mf][nf][0] * alpha;
            float v1 = acc[mf][nf][1] * alpha;
            float v2 = acc[mf][nf][2] * alpha;
            float v3 = acc[mf][nf][3] * alpha;
            if (mode == 0) {
                float* o0 = Cf + z * sC + r0 * (long)N + c0;
                *(float2*)o0 = make_float2(v0, v1);
                *(float2*)(o0 + 8 * (long)N) = make_float2(v2, v3);
            } else {
                __half h0 = __float2half_rn(v0);
                __half h1 = __float2half_rn(v1);
                __half h2 = __float2half_rn(v2);
                __half h3 = __float2half_rn(v3);
                __half* oh0 = Chi + z * sC + r0 * (long)N + c0;
                *(__half2*)oh0 = __halves2half2(h0, h1);
                *(__half2*)(oh0 + 8 * (long)N) = __halves2half2(h2, h3);
                if (mode == 1) {
                    __half l0 = __float2half_rn(v0 - __half2float(h0));
                    __half l1 = __float2half_rn(v1 - __half2float(h1));
                    __half l2 = __float2half_rn(v2 - __half2float(h2));
                    __half l3 = __float2half_rn(v3 - __half2float(h3));
                    __half* ol0 = Clo + z * sC + r0 * (long)N + c0;
                    *(__half2*)ol0 = __halves2half2(l0, l1);
                    *(__half2*)(ol0 + 8 * (long)N) = __halves2half2(l2, l3);
                }
            }
        }
    }
}

// ---------------------------------------------------------------------------
// fp32 -> fp16 hi/lo elementwise split
// ---------------------------------------------------------------------------
__global__ void cvt_split(const float* __restrict__ in,
                          __half* __restrict__ hi,
                          __half* __restrict__ lo, int n)
{
    int i = blockIdx.x * blockDim.x + threadIdx.x;
    if (i >= n) return;
    float v = in[i];
    __half h = __float2half_rn(v);
    hi[i] = h;
    lo[i] = __float2half_rn(v - __half2float(h));
}

// ---------------------------------------------------------------------------
// fp32 [R,C] -> transposed fp16 [C,R] (hi only; batched)
// ---------------------------------------------------------------------------
__global__ void tconvh(const float* __restrict__ in,
                       __half* __restrict__ hi,
                       int R, int C, long sIn, long sOut)
{
    __shared__ float t[32][33];
    const float* ip = in + (long)blockIdx.z * sIn;
    const int c0 = blockIdx.x * 32, r0 = blockIdx.y * 32;
    const int tx = threadIdx.x, ty = threadIdx.y;
    #pragma unroll
    for (int j = 0; j < 4; j++)
        t[ty + 8 * j][tx] = ip[(long)(r0 + ty + 8 * j) * C + c0 + tx];
    __syncthreads();
    const long ob = (long)blockIdx.z * sOut;
    #pragma unroll
    for (int j = 0; j < 4; j++) {
        float v = t[tx][ty + 8 * j];
        hi[ob + (long)(c0 + ty + 8 * j) * R + r0 + tx] = __float2half_rn(v);
    }
}

// ---------------------------------------------------------------------------
// Row softmax over length-2048 rows; fp32 in, fp16 hi/lo out.
// ---------------------------------------------------------------------------
__global__ __launch_bounds__(256)
void softmax_rows(const float* __restrict__ S,
                  __half* __restrict__ Phi,
                  __half* __restrict__ Plo)
{
    const long base = (long)blockIdx.x * S_;
    const float* row = S + base;
    const int tid  = threadIdx.x;
    const int lane = tid & 31;
    const int warp = tid >> 5;
    __shared__ float red[8];

    float v[8];
    float m = -INFINITY;
    #pragma unroll
    for (int i = 0; i < 8; i++) {
        v[i] = row[tid + i * 256];
        m = fmaxf(m, v[i]);
    }
    #pragma unroll
    for (int o = 16; o > 0; o >>= 1) m = fmaxf(m, __shfl_xor_sync(0xffffffffu, m, o));
    if (lane == 0) red[warp] = m;
    __syncthreads();
    m = red[lane & 7];
    #pragma unroll
    for (int o = 4; o > 0; o >>= 1) m = fmaxf(m, __shfl_xor_sync(0xffffffffu, m, o));
    m = __shfl_sync(0xffffffffu, m, 0);

    float s = 0.f;
    #pragma unroll
    for (int i = 0; i < 8; i++) {
        v[i] = __expf(v[i] - m);
        s += v[i];
    }
    #pragma unroll
    for (int o = 16; o > 0; o >>= 1) s += __shfl_xor_sync(0xffffffffu, s, o);
    __syncthreads();
    if (lane == 0) red[warp] = s;
    __syncthreads();
    s = red[lane & 7];
    #pragma unroll
    for (int o = 4; o > 0; o >>= 1) s += __shfl_xor_sync(0xffffffffu, s, o);
    s = __shfl_sync(0xffffffffu, s, 0);

    const float inv = 1.f / s;
    #pragma unroll
    for (int i = 0; i < 8; i++) {
        float p = v[i] * inv;
        __half h = __float2half_rn(p);
        Phi[base + tid + i * 256] = h;
        Plo[base + tid + i * 256] = __float2half_rn(p - __half2float(h));
    }
}

// ---------------------------------------------------------------------------
extern "C" void kernel_launch(void* const* d_in, const int* in_sizes, int n_in,
                              void* d_out, int out_size)
{
    const float* X  = (const float*)d_in[0];
    const float* WQ = (const float*)d_in[1];
    const float* WK = (const float*)d_in[2];
    const float* WV = (const float*)d_in[3];
    const float* WO = (const float*)d_in[4];
    float* Y = (float*)d_out;

    __half *Xhi, *Xlo, *WQt, *WKt, *WVt, *WOt, *Qhi, *Qlo, *Kh, *Vth,
           *Phi, *Plo, *Hhi, *Hlo;
    float *Vf, *Sc;
    cudaGetSymbolAddress((void**)&Xhi, g_Xhi);
    cudaGetSymbolAddress((void**)&Xlo, g_Xlo);
    cudaGetSymbolAddress((void**)&WQt, g_WQt);
    cudaGetSymbolAddress((void**)&WKt, g_WKt);
    cudaGetSymbolAddress((void**)&WVt, g_WVt);
    cudaGetSymbolAddress((void**)&WOt, g_WOt);
    cudaGetSymbolAddress((void**)&Qhi, g_Qhi);
    cudaGetSymbolAddress((void**)&Qlo, g_Qlo);
    cudaGetSymbolAddress((void**)&Kh,  g_Kh);
    cudaGetSymbolAddress((void**)&Vf,  g_Vf);
    cudaGetSymbolAddress((void**)&Vth, g_Vth);
    cudaGetSymbolAddress((void**)&Sc,  g_Sc);
    cudaGetSymbolAddress((void**)&Phi, g_Phi);
    cudaGetSymbolAddress((void**)&Plo, g_Plo);
    cudaGetSymbolAddress((void**)&Hhi, g_Hhi);
    cudaGetSymbolAddress((void**)&Hlo, g_Hlo);

    cudaFuncSetAttribute(gemm3, cudaFuncAttributeMaxDynamicSharedMemorySize,
                         GEMM_SMEM_BYTES);

    dim3 thr(256);
    const size_t smb = GEMM_SMEM_BYTES;

    // Input conversions
    cvt_split<<<(M_TOK * D_) / 256, thr>>>(X, Xhi, Xlo, M_TOK * D_);
    dim3 tW(32, 8);
    tconvh<<<dim3(32, 32, 1), tW>>>(WQ, WQt, D_, D_, 0, 0);
    tconvh<<<dim3(32, 32, 1), tW>>>(WK, WKt, D_, D_, 0, 0);
    tconvh<<<dim3(32, 32, 1), tW>>>(WV, WVt, D_, D_, 0, 0);
    tconvh<<<dim3(32, 32, 1), tW>>>(WO, WOt, D_, D_, 0, 0);

    // Q: hi/lo out (A of scores). K: hi only (B of scores).
    gemm3<<<dim3(4, 64, 1), thr, smb>>>(Xhi, Xlo, WQt, nullptr, Qhi, Qlo,
                                        D_, D_, 0, 0, 0, 1.f, 1);
    gemm3<<<dim3(4, 64, 1), thr, smb>>>(Xhi, Xlo, WKt, nullptr, Kh, nullptr,
                                        D_, D_, 0, 0, 0, 1.f, 2);
    // V: fp32 out, then transpose to [1024,2048] fp16 per batch (B of AV)
    gemm3<<<dim3(4, 64, 1), thr, smb>>>(Xhi, Xlo, WVt, Vf, nullptr, nullptr,
                                        D_, D_, 0, 0, 0, 1.f, 0);
    tconvh<<<dim3(D_ / 32, S_ / 32, B_), tW>>>(Vf, Vth, S_, D_,
                                               (long)S_ * D_, (long)S_ * D_);

    // Scores: per-batch [2048,2048] = Q · K^T / 32 -> fp32
    gemm3<<<dim3(8, 16, 4), thr, smb>>>(Qhi, Qlo, Kh, Sc, nullptr, nullptr,
                                        D_, S_,
                                        (long)S_ * D_, (long)S_ * D_,
                                        (long)S_ * S_, 1.f / 32.f, 0);

    // Softmax -> probs fp16 hi/lo
    softmax_rows<<<B_ * S_, thr>>>(Sc, Phi, Plo);

    // H = A · V : per-batch [2048,1024], B = V^T [1024,2048] -> fp16 hi/lo
    gemm3<<<dim3(4, 16, 4), thr, smb>>>(Phi, Plo, Vth, nullptr, Hhi, Hlo,
                                        S_, D_,
                                        (long)S_ * S_, (long)S_ * D_,
                                        (long)S_ * D_, 1.f, 1);

    // Output: [8192,1024] = H · WOt^T -> fp32 to d_out
    gemm3<<<dim3(4, 64, 1), thr, smb>>>(Hhi, Hlo, WOt, Y, nullptr, nullptr,
                                        D_, D_, 0, 0, 0, 1.f, 0);
}

// round 7
// speedup vs baseline: 4.5737x; 1.5191x over previous
#include <cuda_runtime.h>
#include <cuda_fp16.h>
#include <math.h>
#include <stdint.h>

// ---------------------------------------------------------------------------
// Problem constants
// ---------------------------------------------------------------------------
#define B_  4
#define S_  2048
#define D_  1024
#define M_TOK (B_ * S_)            // 8192

// ---------------------------------------------------------------------------
// Scratch (device globals; allocation in kernel_launch is forbidden)
// ---------------------------------------------------------------------------
__device__ __half g_Xh [M_TOK * D_];
__device__ __half g_WQt[D_ * D_], g_WKt[D_ * D_], g_WVt[D_ * D_], g_WOt[D_ * D_];
__device__ __half g_Qh [M_TOK * D_];
__device__ __half g_Kh [M_TOK * D_];
__device__ float  g_Vf [M_TOK * D_];
__device__ __half g_Vth[M_TOK * D_];
__device__ float  g_Sc [B_ * S_ * S_];
__device__ __half g_Ph [(long)B_ * S_ * S_];
__device__ __half g_Hhi[M_TOK * D_], g_Hlo[M_TOK * D_];

// ---------------------------------------------------------------------------
// Helpers
// ---------------------------------------------------------------------------
__device__ __forceinline__ uint32_t smem_u32(const void* p) {
    uint32_t a;
    asm("{ .reg .u64 t; cvta.to.shared.u64 t, %1; cvt.u32.u64 %0, t; }"
        : "=r"(a) : "l"(p));
    return a;
}

#define CP16(dst, src) \
    asm volatile("cp.async.cg.shared.global [%0], [%1], 16;" \
                 :: "r"((uint32_t)(dst)), "l"(src))

#define LDMX4(r, addr) \
    asm volatile("ldmatrix.sync.aligned.m8n8.x4.shared.b16 {%0,%1,%2,%3}, [%4];" \
                 : "=r"((r)[0]), "=r"((r)[1]), "=r"((r)[2]), "=r"((r)[3]) \
                 : "r"(addr))

// fp16 in, fp32 accumulate
#define MMA_F16(d, a, b0, b1) \
    asm("mma.sync.aligned.m16n8k16.row.col.f32.f16.f16.f32 " \
        "{%0,%1,%2,%3}, {%4,%5,%6,%7}, {%8,%9}, {%0,%1,%2,%3};" \
        : "+f"((d)[0]), "+f"((d)[1]), "+f"((d)[2]), "+f"((d)[3]) \
        : "r"((a)[0]), "r"((a)[1]), "r"((a)[2]), "r"((a)[3]), \
          "r"(b0), "r"(b1))

// ---------------------------------------------------------------------------
// fp16 mma.sync GEMM, templated on number of A terms:
//   ATERMS=1: C = alpha * Ahi · Bhi^T
//   ATERMS=2: C = alpha * (Ahi+Alo) · Bhi^T
// A row-major [M,K], B row-major [N,K]. Output modes:
//   0: fp32 C     1: fp16 hi/lo C     2: fp16 hi-only C
// Batched via blockIdx.z (element strides sA/sB/sC).
// CTA tile 128x256, BK=32, 256 thr (8 warps as 2m x 4n, warp tile 64x64),
// cp.async 3-stage pipeline, 80B row pitch.
// ---------------------------------------------------------------------------
#define ROWB 80

template <int ATERMS>
__global__ __launch_bounds__(256)
void gemm3(const __half* __restrict__ Ahi, const __half* __restrict__ Alo,
           const __half* __restrict__ Bhi,
           float* __restrict__ Cf,
           __half* __restrict__ Chi, __half* __restrict__ Clo,
           int K, int N, long sA, long sB, long sC, float alpha, int mode)
{
    constexpr int AROWS   = 128 * ATERMS;
    constexpr int TROWS   = AROWS + 256;
    constexpr int STAGE_B = TROWS * ROWB;
    constexpr int OFF_ALO = 128 * ROWB;
    constexpr int OFF_B   = AROWS * ROWB;
    constexpr int PER_T   = TROWS / 64;       // 16B chunks per thread per stage

    extern __shared__ char smem[];
    const uint32_t sb = smem_u32(smem);
    const int tid  = threadIdx.x;
    const int wid  = tid >> 5;
    const int lane = tid & 31;
    const long z   = blockIdx.z;

    // ---- global->smem load geometry
    const long rowA = (long)blockIdx.y * 128;
    const long rowB = (long)blockIdx.x * 256;
    const char* gp[PER_T];
    uint32_t sw[PER_T];
    #pragma unroll
    for (int j = 0; j < PER_T; j++) {
        int c = tid + 256 * j;
        int r = c >> 2;
        int col = (c & 3) * 16;
        sw[j] = (uint32_t)(r * ROWB + col);
        if (r < 128)
            gp[j] = (const char*)(Ahi + z * sA + (rowA + r) * (long)K) + col;
        else if (ATERMS == 2 && r < AROWS)
            gp[j] = (const char*)(Alo + z * sA + (rowA + r - 128) * (long)K) + col;
        else
            gp[j] = (const char*)(Bhi + z * sB + (rowB + r - AROWS) * (long)K) + col;
    }

    // ---- ldmatrix geometry: warp tile 64x64
    const int warp_m = wid & 1;               // 2 m-slices of 64
    const int warp_n = wid >> 1;              // 4 n-slices of 64
    const int quad = lane >> 3;
    const int lr8  = lane & 7;
    const uint32_t aBase = sb + (uint32_t)((warp_m * 64 + lr8 + (quad & 1) * 8) * ROWB
                                           + (quad >> 1) * 16);
    const uint32_t bBase = sb + OFF_B + (uint32_t)((warp_n * 64 + lr8 + (quad & 1) * 8) * ROWB
                                                   + (quad >> 1) * 16);

    float acc[4][8][4];
    #pragma unroll
    for (int mf = 0; mf < 4; mf++)
        #pragma unroll
        for (int nf = 0; nf < 8; nf++)
            #pragma unroll
            for (int q = 0; q < 4; q++) acc[mf][nf][q] = 0.f;

    const int nc = K >> 5;                    // K / 32

#define LOADSTAGE(base, ko) do { \
    _Pragma("unroll") \
    for (int j = 0; j < PER_T; j++) CP16((base) + sw[j], gp[j] + (ko)); \
    asm volatile("cp.async.commit_group;" ::: "memory"); \
} while (0)

    // prologue: stages 0 and 1
    LOADSTAGE(sb, 0);
    LOADSTAGE(sb + STAGE_B, 64);

    int s_load = 2;
    int s_cmp  = 0;

    for (int i = 0; i < nc; i++) {
        if (i + 2 < nc) {
            LOADSTAGE(sb + s_load * STAGE_B, (long)(i + 2) * 64);
            asm volatile("cp.async.wait_group 2;" ::: "memory");
        } else if (i + 1 < nc) {
            asm volatile("cp.async.wait_group 1;" ::: "memory");
        } else {
            asm volatile("cp.async.wait_group 0;" ::: "memory");
        }
        __syncthreads();

        const uint32_t stA = aBase + s_cmp * STAGE_B;
        const uint32_t stB = bBase + s_cmp * STAGE_B;

        #pragma unroll
        for (int ks = 0; ks < 2; ks++) {
            uint32_t ah[4][4], bh[4][4];
            #pragma unroll
            for (int mf = 0; mf < 4; mf++)
                LDMX4(ah[mf], stA + mf * (16 * ROWB) + ks * 32);
            #pragma unroll
            for (int ng = 0; ng < 4; ng++)
                LDMX4(bh[ng], stB + ng * (16 * ROWB) + ks * 32);

            #pragma unroll
            for (int ng = 0; ng < 4; ng++)
                #pragma unroll
                for (int mf = 0; mf < 4; mf++) {
                    MMA_F16(acc[mf][ng * 2 + 0], ah[mf], bh[ng][0], bh[ng][2]);
                    MMA_F16(acc[mf][ng * 2 + 1], ah[mf], bh[ng][1], bh[ng][3]);
                }

            if (ATERMS == 2) {
                uint32_t al[4][4];
                #pragma unroll
                for (int mf = 0; mf < 4; mf++)
                    LDMX4(al[mf], stA + OFF_ALO + mf * (16 * ROWB) + ks * 32);
                #pragma unroll
                for (int ng = 0; ng < 4; ng++)
                    #pragma unroll
                    for (int mf = 0; mf < 4; mf++) {
                        MMA_F16(acc[mf][ng * 2 + 0], al[mf], bh[ng][0], bh[ng][2]);
                        MMA_F16(acc[mf][ng * 2 + 1], al[mf], bh[ng][1], bh[ng][3]);
                    }
            }
        }
        __syncthreads();

        s_load = (s_load == 2) ? 0 : s_load + 1;
        s_cmp  = (s_cmp  == 2) ? 0 : s_cmp  + 1;
    }
#undef LOADSTAGE

    // ---- epilogue
    const long baseM = (long)blockIdx.y * 128 + warp_m * 64;
    const long baseN = (long)blockIdx.x * 256 + warp_n * 64;
    const int rq = lane >> 2;                 // row within 8
    const int cq = (lane & 3) * 2;            // col pair
    #pragma unroll
    for (int mf = 0; mf < 4; mf++) {
        #pragma unroll
        for (int nf = 0; nf < 8; nf++) {
            const long r0 = baseM + mf * 16 + rq;
            const long c0 = baseN + nf * 8 + cq;
            float v0 = acc[mf][nf][0] * alpha;
            float v1 = acc[mf][nf][1] * alpha;
            float v2 = acc[mf][nf][2] * alpha;
            float v3 = acc[mf][nf][3] * alpha;
            if (mode == 0) {
                float* o0 = Cf + z * sC + r0 * (long)N + c0;
                *(float2*)o0 = make_float2(v0, v1);
                *(float2*)(o0 + 8 * (long)N) = make_float2(v2, v3);
            } else {
                __half h0 = __float2half_rn(v0);
                __half h1 = __float2half_rn(v1);
                __half h2 = __float2half_rn(v2);
                __half h3 = __float2half_rn(v3);
                __half* oh0 = Chi + z * sC + r0 * (long)N + c0;
                *(__half2*)oh0 = __halves2half2(h0, h1);
                *(__half2*)(oh0 + 8 * (long)N) = __halves2half2(h2, h3);
                if (mode == 1) {
                    __half l0 = __float2half_rn(v0 - __half2float(h0));
                    __half l1 = __float2half_rn(v1 - __half2float(h1));
                    __half l2 = __float2half_rn(v2 - __half2float(h2));
                    __half l3 = __float2half_rn(v3 - __half2float(h3));
                    __half* ol0 = Clo + z * sC + r0 * (long)N + c0;
                    *(__half2*)ol0 = __halves2half2(l0, l1);
                    *(__half2*)(ol0 + 8 * (long)N) = __halves2half2(l2, l3);
                }
            }
        }
    }
}

#define SMEM_AT1 ((128 + 256) * ROWB * 3)     // 92160
#define SMEM_AT2 ((256 + 256) * ROWB * 3)     // 122880

// ---------------------------------------------------------------------------
// fp32 -> fp16 elementwise convert
// ---------------------------------------------------------------------------
__global__ void cvt_h(const float* __restrict__ in,
                      __half* __restrict__ out, int n)
{
    int i = blockIdx.x * blockDim.x + threadIdx.x;
    if (i >= n) return;
    out[i] = __float2half_rn(in[i]);
}

// ---------------------------------------------------------------------------
// fp32 [R,C] -> transposed fp16 [C,R] (batched)
// ---------------------------------------------------------------------------
__global__ void tconvh(const float* __restrict__ in,
                       __half* __restrict__ hi,
                       int R, int C, long sIn, long sOut)
{
    __shared__ float t[32][33];
    const float* ip = in + (long)blockIdx.z * sIn;
    const int c0 = blockIdx.x * 32, r0 = blockIdx.y * 32;
    const int tx = threadIdx.x, ty = threadIdx.y;
    #pragma unroll
    for (int j = 0; j < 4; j++)
        t[ty + 8 * j][tx] = ip[(long)(r0 + ty + 8 * j) * C + c0 + tx];
    __syncthreads();
    const long ob = (long)blockIdx.z * sOut;
    #pragma unroll
    for (int j = 0; j < 4; j++) {
        float v = t[tx][ty + 8 * j];
        hi[ob + (long)(c0 + ty + 8 * j) * R + r0 + tx] = __float2half_rn(v);
    }
}

// ---------------------------------------------------------------------------
// Row softmax over length-2048 rows; fp32 in, fp16 out.
// ---------------------------------------------------------------------------
__global__ __launch_bounds__(256)
void softmax_rows(const float* __restrict__ S, __half* __restrict__ P)
{
    const long base = (long)blockIdx.x * S_;
    const float* row = S + base;
    const int tid  = threadIdx.x;
    const int lane = tid & 31;
    const int warp = tid >> 5;
    __shared__ float red[8];

    float v[8];
    float m = -INFINITY;
    #pragma unroll
    for (int i = 0; i < 8; i++) {
        v[i] = row[tid + i * 256];
        m = fmaxf(m, v[i]);
    }
    #pragma unroll
    for (int o = 16; o > 0; o >>= 1) m = fmaxf(m, __shfl_xor_sync(0xffffffffu, m, o));
    if (lane == 0) red[warp] = m;
    __syncthreads();
    m = red[lane & 7];
    #pragma unroll
    for (int o = 4; o > 0; o >>= 1) m = fmaxf(m, __shfl_xor_sync(0xffffffffu, m, o));
    m = __shfl_sync(0xffffffffu, m, 0);

    float s = 0.f;
    #pragma unroll
    for (int i = 0; i < 8; i++) {
        v[i] = __expf(v[i] - m);
        s += v[i];
    }
    #pragma unroll
    for (int o = 16; o > 0; o >>= 1) s += __shfl_xor_sync(0xffffffffu, s, o);
    __syncthreads();
    if (lane == 0) red[warp] = s;
    __syncthreads();
    s = red[lane & 7];
    #pragma unroll
    for (int o = 4; o > 0; o >>= 1) s += __shfl_xor_sync(0xffffffffu, s, o);
    s = __shfl_sync(0xffffffffu, s, 0);

    const float inv = 1.f / s;
    #pragma unroll
    for (int i = 0; i < 8; i++)
        P[base + tid + i * 256] = __float2half_rn(v[i] * inv);
}

// ---------------------------------------------------------------------------
extern "C" void kernel_launch(void* const* d_in, const int* in_sizes, int n_in,
                              void* d_out, int out_size)
{
    const float* X  = (const float*)d_in[0];
    const float* WQ = (const float*)d_in[1];
    const float* WK = (const float*)d_in[2];
    const float* WV = (const float*)d_in[3];
    const float* WO = (const float*)d_in[4];
    float* Y = (float*)d_out;

    __half *Xh, *WQt, *WKt, *WVt, *WOt, *Qh, *Kh, *Vth, *Ph, *Hhi, *Hlo;
    float *Vf, *Sc;
    cudaGetSymbolAddress((void**)&Xh,  g_Xh);
    cudaGetSymbolAddress((void**)&WQt, g_WQt);
    cudaGetSymbolAddress((void**)&WKt, g_WKt);
    cudaGetSymbolAddress((void**)&WVt, g_WVt);
    cudaGetSymbolAddress((void**)&WOt, g_WOt);
    cudaGetSymbolAddress((void**)&Qh,  g_Qh);
    cudaGetSymbolAddress((void**)&Kh,  g_Kh);
    cudaGetSymbolAddress((void**)&Vf,  g_Vf);
    cudaGetSymbolAddress((void**)&Vth, g_Vth);
    cudaGetSymbolAddress((void**)&Sc,  g_Sc);
    cudaGetSymbolAddress((void**)&Ph,  g_Ph);
    cudaGetSymbolAddress((void**)&Hhi, g_Hhi);
    cudaGetSymbolAddress((void**)&Hlo, g_Hlo);

    cudaFuncSetAttribute(gemm3<1>, cudaFuncAttributeMaxDynamicSharedMemorySize,
                         SMEM_AT1);
    cudaFuncSetAttribute(gemm3<2>, cudaFuncAttributeMaxDynamicSharedMemorySize,
                         SMEM_AT2);

    dim3 thr(256);

    // Input conversions
    cvt_h<<<(M_TOK * D_) / 256, thr>>>(X, Xh, M_TOK * D_);
    dim3 tW(32, 8);
    tconvh<<<dim3(32, 32, 1), tW>>>(WQ, WQt, D_, D_, 0, 0);
    tconvh<<<dim3(32, 32, 1), tW>>>(WK, WKt, D_, D_, 0, 0);
    tconvh<<<dim3(32, 32, 1), tW>>>(WV, WVt, D_, D_, 0, 0);
    tconvh<<<dim3(32, 32, 1), tW>>>(WO, WOt, D_, D_, 0, 0);

    // Projections (single-term A = Xh): Q, K hi-only fp16 out; V fp32 out
    gemm3<1><<<dim3(4, 64, 1), thr, SMEM_AT1>>>(Xh, nullptr, WQt,
                                                nullptr, Qh, nullptr,
                                                D_, D_, 0, 0, 0, 1.f, 2);
    gemm3<1><<<dim3(4, 64, 1), thr, SMEM_AT1>>>(Xh, nullptr, WKt,
                                                nullptr, Kh, nullptr,
                                                D_, D_, 0, 0, 0, 1.f, 2);
    gemm3<1><<<dim3(4, 64, 1), thr, SMEM_AT1>>>(Xh, nullptr, WVt,
                                                Vf, nullptr, nullptr,
                                                D_, D_, 0, 0, 0, 1.f, 0);
    tconvh<<<dim3(D_ / 32, S_ / 32, B_), tW>>>(Vf, Vth, S_, D_,
                                               (long)S_ * D_, (long)S_ * D_);

    // Scores: per-batch [2048,2048] = Q · K^T / 32 -> fp32
    gemm3<1><<<dim3(8, 16, 4), thr, SMEM_AT1>>>(Qh, nullptr, Kh,
                                                Sc, nullptr, nullptr,
                                                D_, S_,
                                                (long)S_ * D_, (long)S_ * D_,
                                                (long)S_ * S_, 1.f / 32.f, 0);

    // Softmax -> probs fp16
    softmax_rows<<<B_ * S_, thr>>>(Sc, Ph);

    // H = A · V : per-batch [2048,1024], B = V^T [1024,2048] -> fp16 hi/lo
    gemm3<1><<<dim3(4, 16, 4), thr, SMEM_AT1>>>(Ph, nullptr, Vth,
                                                nullptr, Hhi, Hlo,
                                                S_, D_,
                                                (long)S_ * S_, (long)S_ * D_,
                                                (long)S_ * D_, 1.f, 1);

    // Output: [8192,1024] = (Hhi+Hlo) · WOt^T -> fp32 to d_out
    gemm3<2><<<dim3(4, 64, 1), thr, SMEM_AT2>>>(Hhi, Hlo, WOt,
                                                Y, nullptr, nullptr,
                                                D_, D_, 0, 0, 0, 1.f, 0);
}

// round 8
// speedup vs baseline: 5.0579x; 1.1059x over previous
#include <cuda_runtime.h>
#include <cuda_fp16.h>
#include <math.h>
#include <stdint.h>

// ---------------------------------------------------------------------------
// Problem constants
// ---------------------------------------------------------------------------
#define B_  4
#define S_  2048
#define D_  1024
#define M_TOK (B_ * S_)            // 8192

// ---------------------------------------------------------------------------
// Scratch (device globals; allocation in kernel_launch is forbidden)
// ---------------------------------------------------------------------------
__device__ __half g_Xh   [M_TOK * D_];
__device__ __half g_Wqkvt[3 * D_ * D_];      // [3072 N-rows, 1024 K]
__device__ __half g_WOt  [D_ * D_];
__device__ __half g_QKV  [(long)M_TOK * 3 * D_];  // [8192, 3072] fp16
__device__ __half g_Vth  [M_TOK * D_];       // per-batch [1024, 2048]
__device__ float  g_Sc   [B_ * S_ * S_];
__device__ __half g_Ph   [(long)B_ * S_ * S_];
__device__ __half g_Hh   [M_TOK * D_];

// ---------------------------------------------------------------------------
// Helpers
// ---------------------------------------------------------------------------
__device__ __forceinline__ uint32_t smem_u32(const void* p) {
    uint32_t a;
    asm("{ .reg .u64 t; cvta.to.shared.u64 t, %1; cvt.u32.u64 %0, t; }"
        : "=r"(a) : "l"(p));
    return a;
}

#define CP16(dst, src) \
    asm volatile("cp.async.cg.shared.global [%0], [%1], 16;" \
                 :: "r"((uint32_t)(dst)), "l"(src))

#define LDMX4(r, addr) \
    asm volatile("ldmatrix.sync.aligned.m8n8.x4.shared.b16 {%0,%1,%2,%3}, [%4];" \
                 : "=r"((r)[0]), "=r"((r)[1]), "=r"((r)[2]), "=r"((r)[3]) \
                 : "r"(addr))

#define MMA_F16(d, a, b0, b1) \
    asm("mma.sync.aligned.m16n8k16.row.col.f32.f16.f16.f32 " \
        "{%0,%1,%2,%3}, {%4,%5,%6,%7}, {%8,%9}, {%0,%1,%2,%3};" \
        : "+f"((d)[0]), "+f"((d)[1]), "+f"((d)[2]), "+f"((d)[3]) \
        : "r"((a)[0]), "r"((a)[1]), "r"((a)[2]), "r"((a)[3]), \
          "r"(b0), "r"(b1))

// ---------------------------------------------------------------------------
// fp16 mma.sync GEMM:  C[M,N] = alpha * A[M,K] · B[N,K]^T
// A row-major with row stride ldA, B row-major with row stride ldB.
// mode 0: fp32 C (row stride ldC).  mode 2: fp16 C (row stride ldC).
// Batched via blockIdx.z (element strides sA/sB/sC).
// CTA tile 128x256, BK=32, 256 thr (8 warps as 2m x 4n, warp tile 64x64),
// cp.async 3-stage pipeline, 80B row pitch.
// ---------------------------------------------------------------------------
#define ROWB 80
#define OFF_B   (128 * ROWB)                 // B rows start at tile row 128
#define STAGE_B (384 * ROWB)                 // 30720
#define GEMM_SMEM (3 * STAGE_B)              // 92160

__global__ __launch_bounds__(256)
void gemmh(const __half* __restrict__ A, const __half* __restrict__ B,
           float* __restrict__ Cf, __half* __restrict__ Ch,
           int K, long ldA, long ldB, long ldC,
           long sA, long sB, long sC, float alpha, int mode)
{
    extern __shared__ char smem[];
    const uint32_t sb = smem_u32(smem);
    const int tid  = threadIdx.x;
    const int wid  = tid >> 5;
    const int lane = tid & 31;
    const long z   = blockIdx.z;

    // ---- global->smem load geometry: 384 rows * 80B; 6 16B-chunks/thread
    const long rowA = (long)blockIdx.y * 128;
    const long rowB = (long)blockIdx.x * 256;
    const char* gp[6];
    uint32_t sw[6];
    #pragma unroll
    for (int j = 0; j < 6; j++) {
        int c = tid + 256 * j;
        int r = c >> 2;
        int col = (c & 3) * 16;
        sw[j] = (uint32_t)(r * ROWB + col);
        if (r < 128)
            gp[j] = (const char*)(A + z * sA + (rowA + r) * ldA) + col;
        else
            gp[j] = (const char*)(B + z * sB + (rowB + r - 128) * ldB) + col;
    }

    // ---- ldmatrix geometry: warp tile 64x64
    const int warp_m = wid & 1;
    const int warp_n = wid >> 1;
    const int quad = lane >> 3;
    const int lr8  = lane & 7;
    const uint32_t aBase = sb + (uint32_t)((warp_m * 64 + lr8 + (quad & 1) * 8) * ROWB
                                           + (quad >> 1) * 16);
    const uint32_t bBase = sb + OFF_B + (uint32_t)((warp_n * 64 + lr8 + (quad & 1) * 8) * ROWB
                                                   + (quad >> 1) * 16);

    float acc[4][8][4];
    #pragma unroll
    for (int mf = 0; mf < 4; mf++)
        #pragma unroll
        for (int nf = 0; nf < 8; nf++)
            #pragma unroll
            for (int q = 0; q < 4; q++) acc[mf][nf][q] = 0.f;

    const int nc = K >> 5;

#define LOADSTAGE(base, ko) do { \
    _Pragma("unroll") \
    for (int j = 0; j < 6; j++) CP16((base) + sw[j], gp[j] + (ko)); \
    asm volatile("cp.async.commit_group;" ::: "memory"); \
} while (0)

    LOADSTAGE(sb, 0);
    LOADSTAGE(sb + STAGE_B, 64);

    int s_load = 2;
    int s_cmp  = 0;

    for (int i = 0; i < nc; i++) {
        if (i + 2 < nc) {
            LOADSTAGE(sb + s_load * STAGE_B, (long)(i + 2) * 64);
            asm volatile("cp.async.wait_group 2;" ::: "memory");
        } else if (i + 1 < nc) {
            asm volatile("cp.async.wait_group 1;" ::: "memory");
        } else {
            asm volatile("cp.async.wait_group 0;" ::: "memory");
        }
        __syncthreads();

        const uint32_t stA = aBase + s_cmp * STAGE_B;
        const uint32_t stB = bBase + s_cmp * STAGE_B;

        #pragma unroll
        for (int ks = 0; ks < 2; ks++) {
            uint32_t ah[4][4], bh[4][4];
            #pragma unroll
            for (int mf = 0; mf < 4; mf++)
                LDMX4(ah[mf], stA + mf * (16 * ROWB) + ks * 32);
            #pragma unroll
            for (int ng = 0; ng < 4; ng++)
                LDMX4(bh[ng], stB + ng * (16 * ROWB) + ks * 32);

            #pragma unroll
            for (int ng = 0; ng < 4; ng++)
                #pragma unroll
                for (int mf = 0; mf < 4; mf++) {
                    MMA_F16(acc[mf][ng * 2 + 0], ah[mf], bh[ng][0], bh[ng][2]);
                    MMA_F16(acc[mf][ng * 2 + 1], ah[mf], bh[ng][1], bh[ng][3]);
                }
        }
        __syncthreads();

        s_load = (s_load == 2) ? 0 : s_load + 1;
        s_cmp  = (s_cmp  == 2) ? 0 : s_cmp  + 1;
    }
#undef LOADSTAGE

    // ---- epilogue
    const long baseM = (long)blockIdx.y * 128 + warp_m * 64;
    const long baseN = (long)blockIdx.x * 256 + warp_n * 64;
    const int rq = lane >> 2;
    const int cq = (lane & 3) * 2;
    #pragma unroll
    for (int mf = 0; mf < 4; mf++) {
        #pragma unroll
        for (int nf = 0; nf < 8; nf++) {
            const long r0 = baseM + mf * 16 + rq;
            const long c0 = baseN + nf * 8 + cq;
            float v0 = acc[mf][nf][0] * alpha;
            float v1 = acc[mf][nf][1] * alpha;
            float v2 = acc[mf][nf][2] * alpha;
            float v3 = acc[mf][nf][3] * alpha;
            if (mode == 0) {
                float* o0 = Cf + z * sC + r0 * ldC + c0;
                *(float2*)o0 = make_float2(v0, v1);
                *(float2*)(o0 + 8 * ldC) = make_float2(v2, v3);
            } else {
                __half* oh0 = Ch + z * sC + r0 * ldC + c0;
                *(__half2*)oh0 = __halves2half2(__float2half_rn(v0),
                                                __float2half_rn(v1));
                *(__half2*)(oh0 + 8 * ldC) = __halves2half2(__float2half_rn(v2),
                                                            __float2half_rn(v3));
            }
        }
    }
}

// ---------------------------------------------------------------------------
// fp32 -> fp16 elementwise convert (float4 vectorized)
// ---------------------------------------------------------------------------
__global__ void cvt_h(const float* __restrict__ in,
                      __half* __restrict__ out, int n4)
{
    int i = blockIdx.x * blockDim.x + threadIdx.x;
    if (i >= n4) return;
    float4 v = ((const float4*)in)[i];
    __half2 a = __halves2half2(__float2half_rn(v.x), __float2half_rn(v.y));
    __half2 b = __halves2half2(__float2half_rn(v.z), __float2half_rn(v.w));
    ((__half2*)out)[2 * i]     = a;
    ((__half2*)out)[2 * i + 1] = b;
}

// ---------------------------------------------------------------------------
// fp32 [R,C] -> transposed fp16 [C,R]
// ---------------------------------------------------------------------------
__global__ void tconvh(const float* __restrict__ in,
                       __half* __restrict__ out, int R, int C)
{
    __shared__ float t[32][33];
    const int c0 = blockIdx.x * 32, r0 = blockIdx.y * 32;
    const int tx = threadIdx.x, ty = threadIdx.y;
    #pragma unroll
    for (int j = 0; j < 4; j++)
        t[ty + 8 * j][tx] = in[(long)(r0 + ty + 8 * j) * C + c0 + tx];
    __syncthreads();
    #pragma unroll
    for (int j = 0; j < 4; j++)
        out[(long)(c0 + ty + 8 * j) * R + r0 + tx] = __float2half_rn(t[tx][ty + 8 * j]);
}

// ---------------------------------------------------------------------------
// fp16 strided [R,C] (row stride ldIn) -> transposed fp16 [C,R] (batched)
// ---------------------------------------------------------------------------
__global__ void tr16(const __half* __restrict__ in,
                     __half* __restrict__ out,
                     int R, int C, long ldIn, long sIn, long sOut)
{
    __shared__ __half t[32][34];
    const __half* ip = in + (long)blockIdx.z * sIn;
    const int c0 = blockIdx.x * 32, r0 = blockIdx.y * 32;
    const int tx = threadIdx.x, ty = threadIdx.y;
    #pragma unroll
    for (int j = 0; j < 4; j++)
        t[ty + 8 * j][tx] = ip[(long)(r0 + ty + 8 * j) * ldIn + c0 + tx];
    __syncthreads();
    __half* op = out + (long)blockIdx.z * sOut;
    #pragma unroll
    for (int j = 0; j < 4; j++)
        op[(long)(c0 + ty + 8 * j) * R + r0 + tx] = t[tx][ty + 8 * j];
}

// ---------------------------------------------------------------------------
// Row softmax over length-2048 rows; fp32 in, fp16 out. float4 loads.
// ---------------------------------------------------------------------------
__global__ __launch_bounds__(256)
void softmax_rows(const float* __restrict__ S, __half* __restrict__ P)
{
    const long base = (long)blockIdx.x * S_;
    const float4* row4 = (const float4*)(S + base);
    const int tid  = threadIdx.x;
    const int lane = tid & 31;
    const int warp = tid >> 5;
    __shared__ float red[8];

    float4 va = row4[tid];
    float4 vb = row4[tid + 256];
    float m = fmaxf(fmaxf(fmaxf(va.x, va.y), fmaxf(va.z, va.w)),
                    fmaxf(fmaxf(vb.x, vb.y), fmaxf(vb.z, vb.w)));
    #pragma unroll
    for (int o = 16; o > 0; o >>= 1) m = fmaxf(m, __shfl_xor_sync(0xffffffffu, m, o));
    if (lane == 0) red[warp] = m;
    __syncthreads();
    m = red[lane & 7];
    #pragma unroll
    for (int o = 4; o > 0; o >>= 1) m = fmaxf(m, __shfl_xor_sync(0xffffffffu, m, o));
    m = __shfl_sync(0xffffffffu, m, 0);

    va.x = __expf(va.x - m); va.y = __expf(va.y - m);
    va.z = __expf(va.z - m); va.w = __expf(va.w - m);
    vb.x = __expf(vb.x - m); vb.y = __expf(vb.y - m);
    vb.z = __expf(vb.z - m); vb.w = __expf(vb.w - m);
    float s = va.x + va.y + va.z + va.w + vb.x + vb.y + vb.z + vb.w;
    #pragma unroll
    for (int o = 16; o > 0; o >>= 1) s += __shfl_xor_sync(0xffffffffu, s, o);
    __syncthreads();
    if (lane == 0) red[warp] = s;
    __syncthreads();
    s = red[lane & 7];
    #pragma unroll
    for (int o = 4; o > 0; o >>= 1) s += __shfl_xor_sync(0xffffffffu, s, o);
    s = __shfl_sync(0xffffffffu, s, 0);

    const float inv = 1.f / s;
    __half2* p2 = (__half2*)(P + base);
    p2[2 * tid]       = __halves2half2(__float2half_rn(va.x * inv),
                                       __float2half_rn(va.y * inv));
    p2[2 * tid + 1]   = __halves2half2(__float2half_rn(va.z * inv),
                                       __float2half_rn(va.w * inv));
    p2[2 * (tid+256)]     = __halves2half2(__float2half_rn(vb.x * inv),
                                           __float2half_rn(vb.y * inv));
    p2[2 * (tid+256) + 1] = __halves2half2(__float2half_rn(vb.z * inv),
                                           __float2half_rn(vb.w * inv));
}

// ---------------------------------------------------------------------------
extern "C" void kernel_launch(void* const* d_in, const int* in_sizes, int n_in,
                              void* d_out, int out_size)
{
    const float* X  = (const float*)d_in[0];
    const float* WQ = (const float*)d_in[1];
    const float* WK = (const float*)d_in[2];
    const float* WV = (const float*)d_in[3];
    const float* WO = (const float*)d_in[4];
    float* Y = (float*)d_out;

    __half *Xh, *Wqkvt, *WOt, *QKV, *Vth, *Ph, *Hh;
    float *Sc;
    cudaGetSymbolAddress((void**)&Xh,    g_Xh);
    cudaGetSymbolAddress((void**)&Wqkvt, g_Wqkvt);
    cudaGetSymbolAddress((void**)&WOt,   g_WOt);
    cudaGetSymbolAddress((void**)&QKV,   g_QKV);
    cudaGetSymbolAddress((void**)&Vth,   g_Vth);
    cudaGetSymbolAddress((void**)&Sc,    g_Sc);
    cudaGetSymbolAddress((void**)&Ph,    g_Ph);
    cudaGetSymbolAddress((void**)&Hh,    g_Hh);

    cudaFuncSetAttribute(gemmh, cudaFuncAttributeMaxDynamicSharedMemorySize,
                         GEMM_SMEM);

    dim3 thr(256);
    dim3 tW(32, 8);
    const long LD3 = 3 * D_;                  // 3072

    // Input conversions
    cvt_h<<<(M_TOK * D_ / 4) / 256, thr>>>(X, Xh, M_TOK * D_ / 4);
    tconvh<<<dim3(32, 32), tW>>>(WQ, Wqkvt,            D_, D_);
    tconvh<<<dim3(32, 32), tW>>>(WK, Wqkvt + D_ * D_,  D_, D_);
    tconvh<<<dim3(32, 32), tW>>>(WV, Wqkvt + 2*D_*D_,  D_, D_);
    tconvh<<<dim3(32, 32), tW>>>(WO, WOt,              D_, D_);

    // Fused QKV projection: [8192, 3072] = Xh · Wqkvt^T, fp16 out
    gemmh<<<dim3(12, 64, 1), thr, GEMM_SMEM>>>(Xh, Wqkvt, nullptr, QKV,
                                               D_, D_, D_, LD3,
                                               0, 0, 0, 1.f, 2);

    // V slice -> per-batch transpose [1024, 2048] fp16
    tr16<<<dim3(D_ / 32, S_ / 32, B_), tW>>>(QKV + 2 * D_, Vth,
                                             S_, D_, LD3,
                                             (long)S_ * LD3, (long)S_ * D_);

    // Scores: per-batch [2048,2048] = Q · K^T / 32 -> fp32
    gemmh<<<dim3(8, 16, 4), thr, GEMM_SMEM>>>(QKV, QKV + D_, Sc, nullptr,
                                              D_, LD3, LD3, S_,
                                              (long)S_ * LD3, (long)S_ * LD3,
                                              (long)S_ * S_, 1.f / 32.f, 0);

    // Softmax -> probs fp16
    softmax_rows<<<B_ * S_, thr>>>(Sc, Ph);

    // H = P · V^T : per-batch [2048,1024], fp16 out
    gemmh<<<dim3(4, 16, 4), thr, GEMM_SMEM>>>(Ph, Vth, nullptr, Hh,
                                              S_, S_, S_, D_,
                                              (long)S_ * S_, (long)S_ * D_,
                                              (long)S_ * D_, 1.f, 2);

    // Output: [8192,1024] = Hh · WOt^T -> fp32 to d_out
    gemmh<<<dim3(4, 64, 1), thr, GEMM_SMEM>>>(Hh, WOt, Y, nullptr,
                                              D_, D_, D_, D_,
                                              0, 0, 0, 1.f, 0);
}

// round 9
// speedup vs baseline: 6.0152x; 1.1893x over previous
#include <cuda_runtime.h>
#include <cuda_fp16.h>
#include <math.h>
#include <stdint.h>

// ---------------------------------------------------------------------------
// Problem constants
// ---------------------------------------------------------------------------
#define B_  4
#define S_  2048
#define D_  1024
#define M_TOK (B_ * S_)            // 8192

// ---------------------------------------------------------------------------
// Scratch (device globals; allocation in kernel_launch is forbidden)
// ---------------------------------------------------------------------------
__device__ __half g_Xh   [M_TOK * D_];
__device__ __half g_Wqkvt[3 * D_ * D_];      // [3072 N-rows, 1024 K]
__device__ __half g_WOt  [D_ * D_];
__device__ __half g_QKV  [(long)M_TOK * 3 * D_];  // [8192, 3072] fp16
__device__ __half g_Vth  [M_TOK * D_];       // per-batch [1024, 2048]
__device__ float  g_Sc   [B_ * S_ * S_];
__device__ __half g_Ph   [(long)B_ * S_ * S_];
__device__ __half g_Hh   [M_TOK * D_];

// ---------------------------------------------------------------------------
// Helpers
// ---------------------------------------------------------------------------
__device__ __forceinline__ uint32_t smem_u32(const void* p) {
    uint32_t a;
    asm("{ .reg .u64 t; cvta.to.shared.u64 t, %1; cvt.u32.u64 %0, t; }"
        : "=r"(a) : "l"(p));
    return a;
}

#define CP16(dst, src) \
    asm volatile("cp.async.cg.shared.global [%0], [%1], 16;" \
                 :: "r"((uint32_t)(dst)), "l"(src))

#define LDMX4(r, addr) \
    asm volatile("ldmatrix.sync.aligned.m8n8.x4.shared.b16 {%0,%1,%2,%3}, [%4];" \
                 : "=r"((r)[0]), "=r"((r)[1]), "=r"((r)[2]), "=r"((r)[3]) \
                 : "r"(addr))

#define MMA_F16(d, a, b0, b1) \
    asm("mma.sync.aligned.m16n8k16.row.col.f32.f16.f16.f32 " \
        "{%0,%1,%2,%3}, {%4,%5,%6,%7}, {%8,%9}, {%0,%1,%2,%3};" \
        : "+f"((d)[0]), "+f"((d)[1]), "+f"((d)[2]), "+f"((d)[3]) \
        : "r"((a)[0]), "r"((a)[1]), "r"((a)[2]), "r"((a)[3]), \
          "r"(b0), "r"(b1))

// ---------------------------------------------------------------------------
// fp16 mma.sync GEMM:  C[M,N] = alpha * A[M,K] · B[N,K]^T
// Template CN = CTA N-tile (256 or 128). CTA M-tile = 128, BK=32, 256 thr.
//   CN=256: 8 warps as 2m x 4n, warp tile 64x64.
//   CN=128: 8 warps as 4m x 2n, warp tile 32x64.
// cp.async 4-stage pipeline, ONE __syncthreads per K-iter, 80B row pitch.
// mode 0: fp32 C (row stride ldC).  mode 2: fp16 C (row stride ldC).
// Batched via blockIdx.z (element strides sA/sB/sC).
// ---------------------------------------------------------------------------
#define ROWB 80

template <int CN>
__global__ __launch_bounds__(256)
void gemmh(const __half* __restrict__ A, const __half* __restrict__ B,
           float* __restrict__ Cf, __half* __restrict__ Ch,
           int K, long ldA, long ldB, long ldC,
           long sA, long sB, long sC, float alpha, int mode)
{
    constexpr int MF      = (CN == 256) ? 4 : 2;   // 16-row m-frags per warp
    constexpr int MSTRIDE = 16 * MF;               // warp m-slice (64 or 32)
    constexpr int TROWS   = 128 + CN;
    constexpr int STAGE   = TROWS * ROWB;
    constexpr int OFFB    = 128 * ROWB;
    constexpr int PER_T   = TROWS / 64;            // 16B chunks per thread

    extern __shared__ char smem[];
    const uint32_t sb = smem_u32(smem);
    const int tid  = threadIdx.x;
    const int wid  = tid >> 5;
    const int lane = tid & 31;
    const long z   = blockIdx.z;

    // ---- global->smem load geometry (64B of K per row per stage)
    const long rowA = (long)blockIdx.y * 128;
    const long rowB = (long)blockIdx.x * CN;
    const char* gp[PER_T];
    uint32_t sw[PER_T];
    #pragma unroll
    for (int j = 0; j < PER_T; j++) {
        int c = tid + 256 * j;
        int r = c >> 2;
        int col = (c & 3) * 16;
        sw[j] = (uint32_t)(r * ROWB + col);
        if (r < 128)
            gp[j] = (const char*)(A + z * sA + (rowA + r) * ldA) + col;
        else
            gp[j] = (const char*)(B + z * sB + (rowB + r - 128) * ldB) + col;
    }

    // ---- ldmatrix geometry
    const int warp_m = (CN == 256) ? (wid & 1) : (wid & 3);
    const int warp_n = (CN == 256) ? (wid >> 1) : (wid >> 2);
    const int quad = lane >> 3;
    const int lr8  = lane & 7;
    const uint32_t aBase = sb + (uint32_t)((warp_m * MSTRIDE + lr8 + (quad & 1) * 8) * ROWB
                                           + (quad >> 1) * 16);
    const uint32_t bBase = sb + OFFB + (uint32_t)((warp_n * 64 + lr8 + (quad & 1) * 8) * ROWB
                                                  + (quad >> 1) * 16);

    float acc[MF][8][4];
    #pragma unroll
    for (int mf = 0; mf < MF; mf++)
        #pragma unroll
        for (int nf = 0; nf < 8; nf++)
            #pragma unroll
            for (int q = 0; q < 4; q++) acc[mf][nf][q] = 0.f;

    const int nc = K >> 5;

#define LOADSTAGE(base, ko) do { \
    _Pragma("unroll") \
    for (int j = 0; j < PER_T; j++) CP16((base) + sw[j], gp[j] + (ko)); \
    asm volatile("cp.async.commit_group;" ::: "memory"); \
} while (0)

    // prologue: stages 0 and 1
    LOADSTAGE(sb, 0);
    LOADSTAGE(sb + STAGE, 64);

    for (int i = 0; i < nc; i++) {
        // load stage (i+2)%4; it aliases neither the compute stage i%4 nor
        // stage (i+1)%4 (already loaded), and its previous consumers (iter
        // i-2) are all past the barrier below.
        if (i + 2 < nc) {
            LOADSTAGE(sb + ((i + 2) & 3) * STAGE, (long)(i + 2) * 64);
            asm volatile("cp.async.wait_group 2;" ::: "memory");
        } else if (i + 1 < nc) {
            asm volatile("cp.async.wait_group 1;" ::: "memory");
        } else {
            asm volatile("cp.async.wait_group 0;" ::: "memory");
        }
        __syncthreads();

        const uint32_t stA = aBase + (i & 3) * STAGE;
        const uint32_t stB = bBase + (i & 3) * STAGE;

        #pragma unroll
        for (int ks = 0; ks < 2; ks++) {
            uint32_t ah[MF][4], bh[4][4];
            #pragma unroll
            for (int mf = 0; mf < MF; mf++)
                LDMX4(ah[mf], stA + mf * (16 * ROWB) + ks * 32);
            #pragma unroll
            for (int ng = 0; ng < 4; ng++)
                LDMX4(bh[ng], stB + ng * (16 * ROWB) + ks * 32);

            #pragma unroll
            for (int ng = 0; ng < 4; ng++)
                #pragma unroll
                for (int mf = 0; mf < MF; mf++) {
                    MMA_F16(acc[mf][ng * 2 + 0], ah[mf], bh[ng][0], bh[ng][2]);
                    MMA_F16(acc[mf][ng * 2 + 1], ah[mf], bh[ng][1], bh[ng][3]);
                }
        }
    }
#undef LOADSTAGE

    // ---- epilogue
    const long baseM = (long)blockIdx.y * 128 + warp_m * MSTRIDE;
    const long baseN = (long)blockIdx.x * CN + warp_n * 64;
    const int rq = lane >> 2;
    const int cq = (lane & 3) * 2;
    #pragma unroll
    for (int mf = 0; mf < MF; mf++) {
        #pragma unroll
        for (int nf = 0; nf < 8; nf++) {
            const long r0 = baseM + mf * 16 + rq;
            const long c0 = baseN + nf * 8 + cq;
            float v0 = acc[mf][nf][0] * alpha;
            float v1 = acc[mf][nf][1] * alpha;
            float v2 = acc[mf][nf][2] * alpha;
            float v3 = acc[mf][nf][3] * alpha;
            if (mode == 0) {
                float* o0 = Cf + z * sC + r0 * ldC + c0;
                *(float2*)o0 = make_float2(v0, v1);
                *(float2*)(o0 + 8 * ldC) = make_float2(v2, v3);
            } else {
                __half* oh0 = Ch + z * sC + r0 * ldC + c0;
                *(__half2*)oh0 = __halves2half2(__float2half_rn(v0),
                                                __float2half_rn(v1));
                *(__half2*)(oh0 + 8 * ldC) = __halves2half2(__float2half_rn(v2),
                                                            __float2half_rn(v3));
            }
        }
    }
}

#define SMEM_CN256 (4 * (128 + 256) * ROWB)   // 122880
#define SMEM_CN128 (4 * (128 + 128) * ROWB)   // 81920

// ---------------------------------------------------------------------------
// Fused prep: X fp32->fp16 convert + 4 weight transposes, one launch.
// Blocks [0, 8192): X convert (256 thr * 4 float4).
// Blocks [8192, 12288): W transposes, 1024 blocks each for WQ,WK,WV,WO.
// ---------------------------------------------------------------------------
__global__ __launch_bounds__(256)
void prep(const float* __restrict__ X,
          const float* __restrict__ WQ, const float* __restrict__ WK,
          const float* __restrict__ WV, const float* __restrict__ WO,
          __half* __restrict__ Xh, __half* __restrict__ Wqkvt,
          __half* __restrict__ WOt)
{
    __shared__ float t[32][33];
    const int bid = blockIdx.x;
    const int tid = threadIdx.x;

    if (bid < 8192) {
        int i = bid * 256 + tid;
        float4 v = ((const float4*)X)[i];
        ((__half2*)Xh)[2 * i]     = __halves2half2(__float2half_rn(v.x),
                                                   __float2half_rn(v.y));
        ((__half2*)Xh)[2 * i + 1] = __halves2half2(__float2half_rn(v.z),
                                                   __float2half_rn(v.w));
        return;
    }

    const int wb = bid - 8192;
    const int wi = wb >> 10;                  // which weight
    const int b  = wb & 1023;
    const float* src = (wi == 0) ? WQ : (wi == 1) ? WK : (wi == 2) ? WV : WO;
    __half* dst = (wi == 3) ? WOt : (Wqkvt + (long)wi * D_ * D_);

    const int c0 = (b & 31) * 32, r0 = (b >> 5) * 32;
    const int tx = tid & 31, ty = tid >> 5;
    #pragma unroll
    for (int j = 0; j < 4; j++)
        t[ty + 8 * j][tx] = src[(long)(r0 + ty + 8 * j) * D_ + c0 + tx];
    __syncthreads();
    #pragma unroll
    for (int j = 0; j < 4; j++)
        dst[(long)(c0 + ty + 8 * j) * D_ + r0 + tx] =
            __float2half_rn(t[tx][ty + 8 * j]);
}

// ---------------------------------------------------------------------------
// fp16 strided [R,C] (row stride ldIn) -> transposed fp16 [C,R] (batched)
// ---------------------------------------------------------------------------
__global__ void tr16(const __half* __restrict__ in,
                     __half* __restrict__ out,
                     int R, int C, long ldIn, long sIn, long sOut)
{
    __shared__ __half t[32][34];
    const __half* ip = in + (long)blockIdx.z * sIn;
    const int c0 = blockIdx.x * 32, r0 = blockIdx.y * 32;
    const int tx = threadIdx.x, ty = threadIdx.y;
    #pragma unroll
    for (int j = 0; j < 4; j++)
        t[ty + 8 * j][tx] = ip[(long)(r0 + ty + 8 * j) * ldIn + c0 + tx];
    __syncthreads();
    __half* op = out + (long)blockIdx.z * sOut;
    #pragma unroll
    for (int j = 0; j < 4; j++)
        op[(long)(c0 + ty + 8 * j) * R + r0 + tx] = t[tx][ty + 8 * j];
}

// ---------------------------------------------------------------------------
// Row softmax over length-2048 rows; fp32 in, fp16 out. float4 loads.
// ---------------------------------------------------------------------------
__global__ __launch_bounds__(256)
void softmax_rows(const float* __restrict__ S, __half* __restrict__ P)
{
    const long base = (long)blockIdx.x * S_;
    const float4* row4 = (const float4*)(S + base);
    const int tid  = threadIdx.x;
    const int lane = tid & 31;
    const int warp = tid >> 5;
    __shared__ float red[8];

    float4 va = row4[tid];
    float4 vb = row4[tid + 256];
    float m = fmaxf(fmaxf(fmaxf(va.x, va.y), fmaxf(va.z, va.w)),
                    fmaxf(fmaxf(vb.x, vb.y), fmaxf(vb.z, vb.w)));
    #pragma unroll
    for (int o = 16; o > 0; o >>= 1) m = fmaxf(m, __shfl_xor_sync(0xffffffffu, m, o));
    if (lane == 0) red[warp] = m;
    __syncthreads();
    m = red[lane & 7];
    #pragma unroll
    for (int o = 4; o > 0; o >>= 1) m = fmaxf(m, __shfl_xor_sync(0xffffffffu, m, o));
    m = __shfl_sync(0xffffffffu, m, 0);

    va.x = __expf(va.x - m); va.y = __expf(va.y - m);
    va.z = __expf(va.z - m); va.w = __expf(va.w - m);
    vb.x = __expf(vb.x - m); vb.y = __expf(vb.y - m);
    vb.z = __expf(vb.z - m); vb.w = __expf(vb.w - m);
    float s = va.x + va.y + va.z + va.w + vb.x + vb.y + vb.z + vb.w;
    #pragma unroll
    for (int o = 16; o > 0; o >>= 1) s += __shfl_xor_sync(0xffffffffu, s, o);
    __syncthreads();
    if (lane == 0) red[warp] = s;
    __syncthreads();
    s = red[lane & 7];
    #pragma unroll
    for (int o = 4; o > 0; o >>= 1) s += __shfl_xor_sync(0xffffffffu, s, o);
    s = __shfl_sync(0xffffffffu, s, 0);

    const float inv = 1.f / s;
    __half2* p2 = (__half2*)(P + base);
    p2[2 * tid]       = __halves2half2(__float2half_rn(va.x * inv),
                                       __float2half_rn(va.y * inv));
    p2[2 * tid + 1]   = __halves2half2(__float2half_rn(va.z * inv),
                                       __float2half_rn(va.w * inv));
    p2[2 * (tid+256)]     = __halves2half2(__float2half_rn(vb.x * inv),
                                           __float2half_rn(vb.y * inv));
    p2[2 * (tid+256) + 1] = __halves2half2(__float2half_rn(vb.z * inv),
                                           __float2half_rn(vb.w * inv));
}

// ---------------------------------------------------------------------------
extern "C" void kernel_launch(void* const* d_in, const int* in_sizes, int n_in,
                              void* d_out, int out_size)
{
    const float* X  = (const float*)d_in[0];
    const float* WQ = (const float*)d_in[1];
    const float* WK = (const float*)d_in[2];
    const float* WV = (const float*)d_in[3];
    const float* WO = (const float*)d_in[4];
    float* Y = (float*)d_out;

    __half *Xh, *Wqkvt, *WOt, *QKV, *Vth, *Ph, *Hh;
    float *Sc;
    cudaGetSymbolAddress((void**)&Xh,    g_Xh);
    cudaGetSymbolAddress((void**)&Wqkvt, g_Wqkvt);
    cudaGetSymbolAddress((void**)&WOt,   g_WOt);
    cudaGetSymbolAddress((void**)&QKV,   g_QKV);
    cudaGetSymbolAddress((void**)&Vth,   g_Vth);
    cudaGetSymbolAddress((void**)&Sc,    g_Sc);
    cudaGetSymbolAddress((void**)&Ph,    g_Ph);
    cudaGetSymbolAddress((void**)&Hh,    g_Hh);

    cudaFuncSetAttribute(gemmh<256>, cudaFuncAttributeMaxDynamicSharedMemorySize,
                         SMEM_CN256);
    cudaFuncSetAttribute(gemmh<128>, cudaFuncAttributeMaxDynamicSharedMemorySize,
                         SMEM_CN128);

    dim3 thr(256);
    dim3 tW(32, 8);
    const long LD3 = 3 * D_;                  // 3072

    // Fused input conversions (X convert + 4 W transposes)
    prep<<<8192 + 4096, thr>>>(X, WQ, WK, WV, WO, Xh, Wqkvt, WOt);

    // Fused QKV projection: [8192, 3072] = Xh · Wqkvt^T, fp16 out
    gemmh<128><<<dim3(24, 64, 1), thr, SMEM_CN128>>>(Xh, Wqkvt, nullptr, QKV,
                                                     D_, D_, D_, LD3,
                                                     0, 0, 0, 1.f, 2);

    // V slice -> per-batch transpose [1024, 2048] fp16
    tr16<<<dim3(D_ / 32, S_ / 32, B_), tW>>>(QKV + 2 * D_, Vth,
                                             S_, D_, LD3,
                                             (long)S_ * LD3, (long)S_ * D_);

    // Scores: per-batch [2048,2048] = Q · K^T / 32 -> fp32
    gemmh<128><<<dim3(16, 16, 4), thr, SMEM_CN128>>>(QKV, QKV + D_, Sc, nullptr,
                                                     D_, LD3, LD3, S_,
                                                     (long)S_ * LD3, (long)S_ * LD3,
                                                     (long)S_ * S_, 1.f / 32.f, 0);

    // Softmax -> probs fp16
    softmax_rows<<<B_ * S_, thr>>>(Sc, Ph);

    // H = P · V^T : per-batch [2048,1024], fp16 out
    gemmh<256><<<dim3(4, 16, 4), thr, SMEM_CN256>>>(Ph, Vth, nullptr, Hh,
                                                    S_, S_, S_, D_,
                                                    (long)S_ * S_, (long)S_ * D_,
                                                    (long)S_ * D_, 1.f, 2);

    // Output: [8192,1024] = Hh · WOt^T -> fp32 to d_out
    gemmh<256><<<dim3(4, 64, 1), thr, SMEM_CN256>>>(Hh, WOt, Y, nullptr,
                                                    D_, D_, D_, D_,
                                                    0, 0, 0, 1.f, 0);
}

// round 10
// speedup vs baseline: 6.3130x; 1.0495x over previous
#include <cuda_runtime.h>
#include <cuda_fp16.h>
#include <math.h>
#include <stdint.h>

// ---------------------------------------------------------------------------
// Problem constants
// ---------------------------------------------------------------------------
#define B_  4
#define S_  2048
#define D_  1024
#define M_TOK (B_ * S_)            // 8192

// ---------------------------------------------------------------------------
// Scratch (device globals; allocation in kernel_launch is forbidden)
// ---------------------------------------------------------------------------
__device__ __half g_Xh   [M_TOK * D_];
__device__ __half g_Wqkvt[3 * D_ * D_];      // [3072 N-rows, 1024 K]
__device__ __half g_WOt  [D_ * D_];
__device__ __half g_QKV  [(long)M_TOK * 3 * D_];  // [8192, 3072] fp16
__device__ __half g_Vth  [M_TOK * D_];       // per-batch [1024, 2048]
__device__ float  g_Sc   [B_ * S_ * S_];
__device__ __half g_Ph   [(long)B_ * S_ * S_];
__device__ __half g_Hh   [M_TOK * D_];

// ---------------------------------------------------------------------------
// Helpers
// ---------------------------------------------------------------------------
__device__ __forceinline__ uint32_t smem_u32(const void* p) {
    uint32_t a;
    asm("{ .reg .u64 t; cvta.to.shared.u64 t, %1; cvt.u32.u64 %0, t; }"
        : "=r"(a) : "l"(p));
    return a;
}

#define CP16(dst, src) \
    asm volatile("cp.async.cg.shared.global [%0], [%1], 16;" \
                 :: "r"((uint32_t)(dst)), "l"(src))

#define LDMX4(r, addr) \
    asm volatile("ldmatrix.sync.aligned.m8n8.x4.shared.b16 {%0,%1,%2,%3}, [%4];" \
                 : "=r"((r)[0]), "=r"((r)[1]), "=r"((r)[2]), "=r"((r)[3]) \
                 : "r"(addr))

#define MMA_F16(d, a, b0, b1) \
    asm("mma.sync.aligned.m16n8k16.row.col.f32.f16.f16.f32 " \
        "{%0,%1,%2,%3}, {%4,%5,%6,%7}, {%8,%9}, {%0,%1,%2,%3};" \
        : "+f"((d)[0]), "+f"((d)[1]), "+f"((d)[2]), "+f"((d)[3]) \
        : "r"((a)[0]), "r"((a)[1]), "r"((a)[2]), "r"((a)[3]), \
          "r"(b0), "r"(b1))

// ---------------------------------------------------------------------------
// fp16 mma.sync GEMM:  C[M,N] = alpha * A[M,K] · B[N,K]^T
// CTA tile 128x128, BK=32, 256 thr (8 warps as 4m x 2n, warp tile 32x64).
// cp.async 4-stage pipeline, ONE __syncthreads per K-iter, 80B row pitch,
// ALL ldmatrix of both ks-steps batched before the MMAs (ILP), 2 CTAs/SM.
// mode 0: fp32 C (row stride ldC).  mode 2: fp16 C (row stride ldC).
// Batched via blockIdx.z (element strides sA/sB/sC).
// ---------------------------------------------------------------------------
#define ROWB 80
#define TROWS 256
#define STAGE (TROWS * ROWB)                 // 20480
#define OFFB  (128 * ROWB)
#define GEMM_SMEM (4 * STAGE)                // 81920

__global__ __launch_bounds__(256, 2)
void gemmh(const __half* __restrict__ A, const __half* __restrict__ B,
           float* __restrict__ Cf, __half* __restrict__ Ch,
           int K, long ldA, long ldB, long ldC,
           long sA, long sB, long sC, float alpha, int mode)
{
    extern __shared__ char smem[];
    const uint32_t sb = smem_u32(smem);
    const int tid  = threadIdx.x;
    const int wid  = tid >> 5;
    const int lane = tid & 31;
    const long z   = blockIdx.z;

    // ---- global->smem load geometry: 256 rows * 64B of K; 4 chunks/thread
    const long rowA = (long)blockIdx.y * 128;
    const long rowB = (long)blockIdx.x * 128;
    const char* gp[4];
    uint32_t sw[4];
    #pragma unroll
    for (int j = 0; j < 4; j++) {
        int c = tid + 256 * j;
        int r = c >> 2;
        int col = (c & 3) * 16;
        sw[j] = (uint32_t)(r * ROWB + col);
        if (r < 128)
            gp[j] = (const char*)(A + z * sA + (rowA + r) * ldA) + col;
        else
            gp[j] = (const char*)(B + z * sB + (rowB + r - 128) * ldB) + col;
    }

    // ---- ldmatrix geometry: warp tile 32x64 (4m x 2n warps)
    const int warp_m = wid & 3;
    const int warp_n = wid >> 2;
    const int quad = lane >> 3;
    const int lr8  = lane & 7;
    const uint32_t aBase = sb + (uint32_t)((warp_m * 32 + lr8 + (quad & 1) * 8) * ROWB
                                           + (quad >> 1) * 16);
    const uint32_t bBase = sb + OFFB + (uint32_t)((warp_n * 64 + lr8 + (quad & 1) * 8) * ROWB
                                                  + (quad >> 1) * 16);

    float acc[2][8][4];
    #pragma unroll
    for (int mf = 0; mf < 2; mf++)
        #pragma unroll
        for (int nf = 0; nf < 8; nf++)
            #pragma unroll
            for (int q = 0; q < 4; q++) acc[mf][nf][q] = 0.f;

    const int nc = K >> 5;

#define LOADSTAGE(base, ko) do { \
    _Pragma("unroll") \
    for (int j = 0; j < 4; j++) CP16((base) + sw[j], gp[j] + (ko)); \
    asm volatile("cp.async.commit_group;" ::: "memory"); \
} while (0)

    LOADSTAGE(sb, 0);
    LOADSTAGE(sb + STAGE, 64);

    for (int i = 0; i < nc; i++) {
        if (i + 2 < nc) {
            LOADSTAGE(sb + ((i + 2) & 3) * STAGE, (long)(i + 2) * 64);
            asm volatile("cp.async.wait_group 2;" ::: "memory");
        } else if (i + 1 < nc) {
            asm volatile("cp.async.wait_group 1;" ::: "memory");
        } else {
            asm volatile("cp.async.wait_group 0;" ::: "memory");
        }
        __syncthreads();

        const uint32_t stA = aBase + (i & 3) * STAGE;
        const uint32_t stB = bBase + (i & 3) * STAGE;

        // Batch ALL ldmatrix for both ks-steps; ks=1 loads complete under
        // the shadow of ks=0 MMAs.
        uint32_t ah[2][2][4], bh[2][4][4];
        #pragma unroll
        for (int ks = 0; ks < 2; ks++) {
            #pragma unroll
            for (int mf = 0; mf < 2; mf++)
                LDMX4(ah[ks][mf], stA + mf * (16 * ROWB) + ks * 32);
            #pragma unroll
            for (int ng = 0; ng < 4; ng++)
                LDMX4(bh[ks][ng], stB + ng * (16 * ROWB) + ks * 32);
        }
        #pragma unroll
        for (int ks = 0; ks < 2; ks++)
            #pragma unroll
            for (int ng = 0; ng < 4; ng++)
                #pragma unroll
                for (int mf = 0; mf < 2; mf++) {
                    MMA_F16(acc[mf][ng * 2 + 0], ah[ks][mf],
                            bh[ks][ng][0], bh[ks][ng][2]);
                    MMA_F16(acc[mf][ng * 2 + 1], ah[ks][mf],
                            bh[ks][ng][1], bh[ks][ng][3]);
                }
    }
#undef LOADSTAGE

    // ---- epilogue
    const long baseM = (long)blockIdx.y * 128 + warp_m * 32;
    const long baseN = (long)blockIdx.x * 128 + warp_n * 64;
    const int rq = lane >> 2;
    const int cq = (lane & 3) * 2;
    #pragma unroll
    for (int mf = 0; mf < 2; mf++) {
        #pragma unroll
        for (int nf = 0; nf < 8; nf++) {
            const long r0 = baseM + mf * 16 + rq;
            const long c0 = baseN + nf * 8 + cq;
            float v0 = acc[mf][nf][0] * alpha;
            float v1 = acc[mf][nf][1] * alpha;
            float v2 = acc[mf][nf][2] * alpha;
            float v3 = acc[mf][nf][3] * alpha;
            if (mode == 0) {
                float* o0 = Cf + z * sC + r0 * ldC + c0;
                *(float2*)o0 = make_float2(v0, v1);
                *(float2*)(o0 + 8 * ldC) = make_float2(v2, v3);
            } else {
                __half* oh0 = Ch + z * sC + r0 * ldC + c0;
                *(__half2*)oh0 = __halves2half2(__float2half_rn(v0),
                                                __float2half_rn(v1));
                *(__half2*)(oh0 + 8 * ldC) = __halves2half2(__float2half_rn(v2),
                                                            __float2half_rn(v3));
            }
        }
    }
}

// ---------------------------------------------------------------------------
// Fused prep: X fp32->fp16 convert + 4 weight transposes, one launch.
// ---------------------------------------------------------------------------
__global__ __launch_bounds__(256)
void prep(const float* __restrict__ X,
          const float* __restrict__ WQ, const float* __restrict__ WK,
          const float* __restrict__ WV, const float* __restrict__ WO,
          __half* __restrict__ Xh, __half* __restrict__ Wqkvt,
          __half* __restrict__ WOt)
{
    __shared__ float t[32][33];
    const int bid = blockIdx.x;
    const int tid = threadIdx.x;

    if (bid < 8192) {
        int i = bid * 256 + tid;
        float4 v = ((const float4*)X)[i];
        ((__half2*)Xh)[2 * i]     = __halves2half2(__float2half_rn(v.x),
                                                   __float2half_rn(v.y));
        ((__half2*)Xh)[2 * i + 1] = __halves2half2(__float2half_rn(v.z),
                                                   __float2half_rn(v.w));
        return;
    }

    const int wb = bid - 8192;
    const int wi = wb >> 10;
    const int b  = wb & 1023;
    const float* src = (wi == 0) ? WQ : (wi == 1) ? WK : (wi == 2) ? WV : WO;
    __half* dst = (wi == 3) ? WOt : (Wqkvt + (long)wi * D_ * D_);

    const int c0 = (b & 31) * 32, r0 = (b >> 5) * 32;
    const int tx = tid & 31, ty = tid >> 5;
    #pragma unroll
    for (int j = 0; j < 4; j++)
        t[ty + 8 * j][tx] = src[(long)(r0 + ty + 8 * j) * D_ + c0 + tx];
    __syncthreads();
    #pragma unroll
    for (int j = 0; j < 4; j++)
        dst[(long)(c0 + ty + 8 * j) * D_ + r0 + tx] =
            __float2half_rn(t[tx][ty + 8 * j]);
}

// ---------------------------------------------------------------------------
// fp16 strided [R,C] (row stride ldIn) -> transposed fp16 [C,R] (batched)
// ---------------------------------------------------------------------------
__global__ void tr16(const __half* __restrict__ in,
                     __half* __restrict__ out,
                     int R, int C, long ldIn, long sIn, long sOut)
{
    __shared__ __half t[32][34];
    const __half* ip = in + (long)blockIdx.z * sIn;
    const int c0 = blockIdx.x * 32, r0 = blockIdx.y * 32;
    const int tx = threadIdx.x, ty = threadIdx.y;
    #pragma unroll
    for (int j = 0; j < 4; j++)
        t[ty + 8 * j][tx] = ip[(long)(r0 + ty + 8 * j) * ldIn + c0 + tx];
    __syncthreads();
    __half* op = out + (long)blockIdx.z * sOut;
    #pragma unroll
    for (int j = 0; j < 4; j++)
        op[(long)(c0 + ty + 8 * j) * R + r0 + tx] = t[tx][ty + 8 * j];
}

// ---------------------------------------------------------------------------
// Row softmax over length-2048 rows; fp32 in, fp16 out. float4 loads.
// ---------------------------------------------------------------------------
__global__ __launch_bounds__(256)
void softmax_rows(const float* __restrict__ S, __half* __restrict__ P)
{
    const long base = (long)blockIdx.x * S_;
    const float4* row4 = (const float4*)(S + base);
    const int tid  = threadIdx.x;
    const int lane = tid & 31;
    const int warp = tid >> 5;
    __shared__ float red[8];

    float4 va = row4[tid];
    float4 vb = row4[tid + 256];
    float m = fmaxf(fmaxf(fmaxf(va.x, va.y), fmaxf(va.z, va.w)),
                    fmaxf(fmaxf(vb.x, vb.y), fmaxf(vb.z, vb.w)));
    #pragma unroll
    for (int o = 16; o > 0; o >>= 1) m = fmaxf(m, __shfl_xor_sync(0xffffffffu, m, o));
    if (lane == 0) red[warp] = m;
    __syncthreads();
    m = red[lane & 7];
    #pragma unroll
    for (int o = 4; o > 0; o >>= 1) m = fmaxf(m, __shfl_xor_sync(0xffffffffu, m, o));
    m = __shfl_sync(0xffffffffu, m, 0);

    va.x = __expf(va.x - m); va.y = __expf(va.y - m);
    va.z = __expf(va.z - m); va.w = __expf(va.w - m);
    vb.x = __expf(vb.x - m); vb.y = __expf(vb.y - m);
    vb.z = __expf(vb.z - m); vb.w = __expf(vb.w - m);
    float s = va.x + va.y + va.z + va.w + vb.x + vb.y + vb.z + vb.w;
    #pragma unroll
    for (int o = 16; o > 0; o >>= 1) s += __shfl_xor_sync(0xffffffffu, s, o);
    __syncthreads();
    if (lane == 0) red[warp] = s;
    __syncthreads();
    s = red[lane & 7];
    #pragma unroll
    for (int o = 4; o > 0; o >>= 1) s += __shfl_xor_sync(0xffffffffu, s, o);
    s = __shfl_sync(0xffffffffu, s, 0);

    const float inv = 1.f / s;
    __half2* p2 = (__half2*)(P + base);
    p2[2 * tid]       = __halves2half2(__float2half_rn(va.x * inv),
                                       __float2half_rn(va.y * inv));
    p2[2 * tid + 1]   = __halves2half2(__float2half_rn(va.z * inv),
                                       __float2half_rn(va.w * inv));
    p2[2 * (tid+256)]     = __halves2half2(__float2half_rn(vb.x * inv),
                                           __float2half_rn(vb.y * inv));
    p2[2 * (tid+256) + 1] = __halves2half2(__float2half_rn(vb.z * inv),
                                           __float2half_rn(vb.w * inv));
}

// ---------------------------------------------------------------------------
extern "C" void kernel_launch(void* const* d_in, const int* in_sizes, int n_in,
                              void* d_out, int out_size)
{
    const float* X  = (const float*)d_in[0];
    const float* WQ = (const float*)d_in[1];
    const float* WK = (const float*)d_in[2];
    const float* WV = (const float*)d_in[3];
    const float* WO = (const float*)d_in[4];
    float* Y = (float*)d_out;

    __half *Xh, *Wqkvt, *WOt, *QKV, *Vth, *Ph, *Hh;
    float *Sc;
    cudaGetSymbolAddress((void**)&Xh,    g_Xh);
    cudaGetSymbolAddress((void**)&Wqkvt, g_Wqkvt);
    cudaGetSymbolAddress((void**)&WOt,   g_WOt);
    cudaGetSymbolAddress((void**)&QKV,   g_QKV);
    cudaGetSymbolAddress((void**)&Vth,   g_Vth);
    cudaGetSymbolAddress((void**)&Sc,    g_Sc);
    cudaGetSymbolAddress((void**)&Ph,    g_Ph);
    cudaGetSymbolAddress((void**)&Hh,    g_Hh);

    cudaFuncSetAttribute(gemmh, cudaFuncAttributeMaxDynamicSharedMemorySize,
                         GEMM_SMEM);

    dim3 thr(256);
    dim3 tW(32, 8);
    const long LD3 = 3 * D_;                  // 3072

    // Fused input conversions (X convert + 4 W transposes)
    prep<<<8192 + 4096, thr>>>(X, WQ, WK, WV, WO, Xh, Wqkvt, WOt);

    // Fused QKV projection: [8192, 3072] = Xh · Wqkvt^T, fp16 out
    gemmh<<<dim3(24, 64, 1), thr, GEMM_SMEM>>>(Xh, Wqkvt, nullptr, QKV,
                                               D_, D_, D_, LD3,
                                               0, 0, 0, 1.f, 2);

    // V slice -> per-batch transpose [1024, 2048] fp16
    tr16<<<dim3(D_ / 32, S_ / 32, B_), tW>>>(QKV + 2 * D_, Vth,
                                             S_, D_, LD3,
                                             (long)S_ * LD3, (long)S_ * D_);

    // Scores: per-batch [2048,2048] = Q · K^T / 32 -> fp32
    gemmh<<<dim3(16, 16, 4), thr, GEMM_SMEM>>>(QKV, QKV + D_, Sc, nullptr,
                                               D_, LD3, LD3, S_,
                                               (long)S_ * LD3, (long)S_ * LD3,
                                               (long)S_ * S_, 1.f / 32.f, 0);

    // Softmax -> probs fp16
    softmax_rows<<<B_ * S_, thr>>>(Sc, Ph);

    // H = P · V^T : per-batch [2048,1024], fp16 out
    gemmh<<<dim3(8, 16, 4), thr, GEMM_SMEM>>>(Ph, Vth, nullptr, Hh,
                                              S_, S_, S_, D_,
                                              (long)S_ * S_, (long)S_ * D_,
                                              (long)S_ * D_, 1.f, 2);

    // Output: [8192,1024] = Hh · WOt^T -> fp32 to d_out
    gemmh<<<dim3(8, 64, 1), thr, GEMM_SMEM>>>(Hh, WOt, Y, nullptr,
                                              D_, D_, D_, D_,
                                              0, 0, 0, 1.f, 0);
}